// round 1
// baseline (speedup 1.0000x reference)
#include <cuda_runtime.h>
#include <cuda_bf16.h>
#include <mma.h>

using namespace nvcuda;

// Problem constants
#define BATCH 4
#define SEQ   1024
#define DMODEL 4096
#define HEADS 32
#define HDIM  128
#define ROTARY 32
#define MAXPOS 10000

// GEMM tiling
#define BM 128
#define BN 128
#define BK 32
#define APAD 4
#define BPAD 4

// Scratch (device globals; no allocation allowed)
__device__ float g_q[(long)BATCH*SEQ*HEADS*HDIM];       // [B,S,H,HD]  64MB
__device__ float g_k[(long)BATCH*SEQ*HEADS*HDIM];
__device__ float g_v[(long)BATCH*SEQ*HEADS*HDIM];
__device__ float g_o[(long)BATCH*SEQ*HEADS*HDIM];
__device__ float g_sc[(long)BATCH*HEADS*SEQ*SEQ];       // [B,H,S,S]  512MB

// ---------------------------------------------------------------------------
// Generic batched GEMM: C[M,N] = A[M,K] * B[K,N]
//   A row-major (lda). B row-major (ldb) unless transB, in which case
//   logical B[k,n] = Bp[n*ldb + k].
//   Batch index z decomposed as (b = z / Hb, h = z % Hb) with separate strides.
//   M,N,K all multiples of tile sizes (guaranteed by call sites). No bias here.
// ---------------------------------------------------------------------------
__global__ __launch_bounds__(256) void gemm_kernel(
    const float* __restrict__ Ab, const float* __restrict__ Bb,
    float* __restrict__ Cb,
    int M, int N, int K,
    int lda, int ldb, int ldc,
    long sAb, long sAh, long sBb, long sBh, long sCb, long sCh,
    int Hb, int transB)
{
    __shared__ float As[BM][BK + APAD];
    __shared__ float Bs[BK][BN + BPAD];

    int z = blockIdx.z;
    int bb = z / Hb, hh = z % Hb;
    const float* A = Ab + bb * sAb + hh * sAh;
    const float* B = Bb + bb * sBb + hh * sBh;
    float*       C = Cb + bb * sCb + hh * sCh;

    int rowBase = blockIdx.y * BM;
    int colBase = blockIdx.x * BN;

    int tid = threadIdx.x;
    int wid = tid >> 5;
    int warpRow = (wid & 3) * 32;   // 4 warps along M (32 rows each)
    int warpCol = (wid >> 2) * 64;  // 2 warps along N (64 cols each)

    wmma::fragment<wmma::accumulator, 16, 16, 8, float> c[2][4];
#pragma unroll
    for (int i = 0; i < 2; i++)
#pragma unroll
        for (int j = 0; j < 4; j++) wmma::fill_fragment(c[i][j], 0.0f);

    // A-tile loader indexing (also reused for transB B-tile)
    int aRow = tid >> 3;          // 0..31
    int aCol = (tid & 7) * 4;     // 0,4,..,28

    for (int kt = 0; kt < K; kt += BK) {
        // ---- load A tile: 128 x 32 ----
#pragma unroll
        for (int p = 0; p < 4; p++) {
            int r = aRow + p * 32;
            float4 v = *(const float4*)&A[(long)(rowBase + r) * lda + kt + aCol];
            *(float4*)&As[r][aCol] = v;
        }
        // ---- load B tile: 32 x 128 ----
        if (!transB) {
#pragma unroll
            for (int p = 0; p < 4; p++) {
                int r  = (tid >> 5) + p * 8;       // 0..31
                int cc = (tid & 31) * 4;           // 0..124
                float4 v = *(const float4*)&B[(long)(kt + r) * ldb + colBase + cc];
                *(float4*)&Bs[r][cc] = v;
            }
        } else {
#pragma unroll
            for (int p = 0; p < 4; p++) {
                int n = aRow + p * 32;             // output-col index 0..127
                float4 v = *(const float4*)&B[(long)(colBase + n) * ldb + kt + aCol];
                Bs[aCol + 0][n] = v.x;
                Bs[aCol + 1][n] = v.y;
                Bs[aCol + 2][n] = v.z;
                Bs[aCol + 3][n] = v.w;
            }
        }
        __syncthreads();

#pragma unroll
        for (int kk = 0; kk < BK; kk += 8) {
            wmma::fragment<wmma::matrix_a, 16, 16, 8, wmma::precision::tf32, wmma::row_major> a0, a1;
            wmma::load_matrix_sync(a0, &As[warpRow][kk],      BK + APAD);
            wmma::load_matrix_sync(a1, &As[warpRow + 16][kk], BK + APAD);
#pragma unroll
            for (int t = 0; t < a0.num_elements; t++) {
                a0.x[t] = wmma::__float_to_tf32(a0.x[t]);
                a1.x[t] = wmma::__float_to_tf32(a1.x[t]);
            }
#pragma unroll
            for (int j = 0; j < 4; j++) {
                wmma::fragment<wmma::matrix_b, 16, 16, 8, wmma::precision::tf32, wmma::row_major> bf;
                wmma::load_matrix_sync(bf, &Bs[kk][warpCol + 16 * j], BN + BPAD);
#pragma unroll
                for (int t = 0; t < bf.num_elements; t++) bf.x[t] = wmma::__float_to_tf32(bf.x[t]);
                wmma::mma_sync(c[0][j], a0, bf, c[0][j]);
                wmma::mma_sync(c[1][j], a1, bf, c[1][j]);
            }
        }
        __syncthreads();
    }

#pragma unroll
    for (int i = 0; i < 2; i++)
#pragma unroll
        for (int j = 0; j < 4; j++)
            wmma::store_matrix_sync(
                C + (long)(rowBase + warpRow + 16 * i) * ldc + colBase + warpCol + 16 * j,
                c[i][j], ldc, wmma::mem_row_major);
}

// ---------------------------------------------------------------------------
// bias_add: C[m, n] += bias[n], N = 4096, total = 16777216 (vectorized)
// ---------------------------------------------------------------------------
__global__ void bias_add_kernel(float* __restrict__ C, const float* __restrict__ bias)
{
    long i = ((long)blockIdx.x * blockDim.x + threadIdx.x) * 4;
    int n = (int)(i & 4095);
    float4 v = *(float4*)&C[i];
    float4 b = *(const float4*)&bias[n];
    v.x += b.x; v.y += b.y; v.z += b.z; v.w += b.w;
    *(float4*)&C[i] = v;
}

// ---------------------------------------------------------------------------
// rotary: in-place on first 32 channels of [B,S,H,HD]; one thread per (b,s,h)
// Angles in double to match numpy's float64 table at large positions.
// ---------------------------------------------------------------------------
__global__ void rotary_kernel(float* __restrict__ t)
{
    int idx = blockIdx.x * blockDim.x + threadIdx.x;   // 0 .. B*S*H-1
    if (idx >= BATCH * SEQ * HEADS) return;
    int s = (idx >> 5) & (SEQ - 1);
    float* ptr = t + (long)idx * HDIM;
    int pos = MAXPOS - SEQ + s;

    float x[ROTARY];
#pragma unroll
    for (int i = 0; i < ROTARY; i++) x[i] = ptr[i];

    const double log1e4_over16 = 0.57564627324851145;  // ln(10000)/16
#pragma unroll
    for (int i = 0; i < 16; i++) {
        double ang = (double)pos * exp(-(double)i * log1e4_over16);
        double sn, cs;
        sincos(ang, &sn, &cs);
        float a = x[i], b = x[16 + i];
        ptr[2 * i]     = (float)((double)a * cs - (double)b * sn);
        ptr[2 * i + 1] = (float)((double)a * sn + (double)b * cs);
    }
}

// ---------------------------------------------------------------------------
// softmax over k (1024) per row of scores [B,H,S,S], adding scale + attn_bias.
// One warp per row; 32 values per lane.
// ---------------------------------------------------------------------------
__global__ void softmax_kernel(float* __restrict__ scores,
                               const float* __restrict__ bias, float scale)
{
    int warpsPerBlock = blockDim.x >> 5;
    long row = (long)blockIdx.x * warpsPerBlock + (threadIdx.x >> 5);
    int lane = threadIdx.x & 31;
    int q = (int)(row & (SEQ - 1));
    float* p = scores + row * SEQ;
    const float* brow = bias + (long)q * SEQ;

    float vals[32];
    float m = -1e30f;
#pragma unroll
    for (int j = 0; j < 32; j++) {
        float v = p[lane + 32 * j] * scale + brow[lane + 32 * j];
        vals[j] = v;
        m = fmaxf(m, v);
    }
#pragma unroll
    for (int o = 16; o; o >>= 1) m = fmaxf(m, __shfl_xor_sync(0xffffffffu, m, o));
    float s = 0.0f;
#pragma unroll
    for (int j = 0; j < 32; j++) { vals[j] = __expf(vals[j] - m); s += vals[j]; }
#pragma unroll
    for (int o = 16; o; o >>= 1) s += __shfl_xor_sync(0xffffffffu, s, o);
    float inv = 1.0f / s;
#pragma unroll
    for (int j = 0; j < 32; j++) p[lane + 32 * j] = vals[j] * inv;
}

// ---------------------------------------------------------------------------
extern "C" void kernel_launch(void* const* d_in, const int* in_sizes, int n_in,
                              void* d_out, int out_size)
{
    const float* x         = (const float*)d_in[0];
    const float* attn_bias = (const float*)d_in[1];
    const float* wq        = (const float*)d_in[2];
    const float* wq_b      = (const float*)d_in[3];
    const float* wk        = (const float*)d_in[4];
    const float* wk_b      = (const float*)d_in[5];
    const float* wv        = (const float*)d_in[6];
    const float* wv_b      = (const float*)d_in[7];
    const float* wo        = (const float*)d_in[8];
    const float* wo_b      = (const float*)d_in[9];
    float* out = (float*)d_out;

    float *qb, *kb, *vb, *ob, *sc;
    cudaGetSymbolAddress((void**)&qb, g_q);
    cudaGetSymbolAddress((void**)&kb, g_k);
    cudaGetSymbolAddress((void**)&vb, g_v);
    cudaGetSymbolAddress((void**)&ob, g_o);
    cudaGetSymbolAddress((void**)&sc, g_sc);

    dim3 blk(256);
    const long sQKV_b = (long)SEQ * HEADS * HDIM;   // 4194304
    const long sSc_b  = (long)HEADS * SEQ * SEQ;    // 33554432
    const long sSc_h  = (long)SEQ * SEQ;            // 1048576

    // QKV projections: [4096,4096] x [4096,4096] -> [B,S,H*HD]
    gemm_kernel<<<dim3(32, 32, 1), blk>>>(x, wq, qb, 4096, 4096, 4096,
                                          4096, 4096, 4096, 0, 0, 0, 0, 0, 0, 1, 0);
    gemm_kernel<<<dim3(32, 32, 1), blk>>>(x, wk, kb, 4096, 4096, 4096,
                                          4096, 4096, 4096, 0, 0, 0, 0, 0, 0, 1, 0);
    gemm_kernel<<<dim3(32, 32, 1), blk>>>(x, wv, vb, 4096, 4096, 4096,
                                          4096, 4096, 4096, 0, 0, 0, 0, 0, 0, 1, 0);

    bias_add_kernel<<<16384, 256>>>(qb, wq_b);
    bias_add_kernel<<<16384, 256>>>(kb, wk_b);
    bias_add_kernel<<<16384, 256>>>(vb, wv_b);

    rotary_kernel<<<512, 256>>>(qb);
    rotary_kernel<<<512, 256>>>(kb);

    // scores[b,h,q,k] = Q . K^T   (scale & bias folded into softmax)
    gemm_kernel<<<dim3(8, 8, 128), blk>>>(qb, kb, sc, 1024, 1024, 128,
                                          4096, 4096, 1024,
                                          sQKV_b, 128, sQKV_b, 128, sSc_b, sSc_h,
                                          HEADS, 1);

    softmax_kernel<<<16384, 256>>>(sc, attn_bias, 0.08838834764831845f);

    // O[b,s,h,d] = P . V
    gemm_kernel<<<dim3(1, 8, 128), blk>>>(sc, vb, ob, 1024, 128, 1024,
                                          1024, 4096, 4096,
                                          sSc_b, sSc_h, sQKV_b, 128, sQKV_b, 128,
                                          HEADS, 0);

    // out = O . wo + wo_bias
    gemm_kernel<<<dim3(32, 32, 1), blk>>>(ob, wo, out, 4096, 4096, 4096,
                                          4096, 4096, 4096, 0, 0, 0, 0, 0, 0, 1, 0);
    bias_add_kernel<<<16384, 256>>>(out, wo_b);
}

// round 2
// speedup vs baseline: 1.3546x; 1.3546x over previous
#include <cuda_runtime.h>
#include <cuda_bf16.h>
#include <mma.h>
#include <cstdint>

using namespace nvcuda;

// Problem constants
#define BATCH 4
#define SEQ   1024
#define DMODEL 4096
#define HEADS 32
#define HDIM  128
#define ROTARY 32
#define MAXPOS 10000

// GEMM tiling
#define BM 128
#define BN 128
#define BK 32
#define PAD 4          // 4 floats = 16B, keeps cp.async dst 16B-aligned

// Scratch (device globals; no allocation allowed)
__device__ float g_q[(long)BATCH*SEQ*HEADS*HDIM];       // [B,S,H,HD]  64MB
__device__ float g_k[(long)BATCH*SEQ*HEADS*HDIM];
__device__ float g_v[(long)BATCH*SEQ*HEADS*HDIM];
__device__ float g_o[(long)BATCH*SEQ*HEADS*HDIM];
__device__ float g_sc[(long)BATCH*HEADS*SEQ*SEQ];       // [B,H,S,S]  512MB
__device__ float2 g_rot[SEQ*16];                        // rotary cos/sin table

// ---------------------------------------------------------------------------
// cp.async helpers
// ---------------------------------------------------------------------------
__device__ __forceinline__ void cp16(uint32_t saddr, const float* gptr) {
    asm volatile("cp.async.cg.shared.global [%0], [%1], 16;\n" :: "r"(saddr), "l"(gptr));
}
__device__ __forceinline__ void cp_commit() {
    asm volatile("cp.async.commit_group;\n");
}
__device__ __forceinline__ void cp_wait0() {
    asm volatile("cp.async.wait_group 0;\n");
}

// ---------------------------------------------------------------------------
// Double-buffered cp.async GEMM: C[M,N] = A[M,K] * B[K,N]
//   A row-major (lda). If TRANSB: logical B[k,n] = Bp[n*ldb + k].
//   Batch z = (b, h) with separate strides. Tile-exact shapes only.
// ---------------------------------------------------------------------------
template<int TRANSB>
__global__ __launch_bounds__(256) void gemm_db(
    const float* __restrict__ Ab, const float* __restrict__ Bb,
    float* __restrict__ Cb,
    int M, int N, int K,
    int lda, int ldb, int ldc,
    long sAb, long sAh, long sBb, long sBh, long sCb, long sCh,
    int Hb)
{
    constexpr int ASZ = BM * (BK + PAD);                              // floats per A stage
    constexpr int BSZ = TRANSB ? BN * (BK + PAD) : BK * (BN + PAD);   // floats per B stage
    extern __shared__ float sm[];
    float* As = sm;               // [2][ASZ]
    float* Bs = sm + 2 * ASZ;     // [2][BSZ]

    int z = blockIdx.z;
    int bb = z / Hb, hh = z % Hb;
    const float* A = Ab + bb * sAb + hh * sAh;
    const float* B = Bb + bb * sBb + hh * sBh;
    float*       C = Cb + bb * sCb + hh * sCh;

    int rowBase = blockIdx.y * BM;
    int colBase = blockIdx.x * BN;

    int tid = threadIdx.x;
    int wid = tid >> 5;
    int warpRow = (wid & 3) * 32;   // 4 warps along M
    int warpCol = (wid >> 2) * 64;  // 2 warps along N

    // loader indices
    int lr = tid >> 3;          // 0..31
    int lc = (tid & 7) * 4;     // 0,4,..,28
    int br = tid >> 5;          // 0..7
    int bc = (tid & 31) * 4;    // 0..124

    uint32_t sA = (uint32_t)__cvta_generic_to_shared(As);
    uint32_t sB = (uint32_t)__cvta_generic_to_shared(Bs);

    wmma::fragment<wmma::accumulator, 16, 16, 8, float> c[2][4];
#pragma unroll
    for (int i = 0; i < 2; i++)
#pragma unroll
        for (int j = 0; j < 4; j++) wmma::fill_fragment(c[i][j], 0.0f);

    const int KT = K / BK;

    auto loadStage = [&](int kt, int buf) {
        uint32_t a0 = sA + (uint32_t)(buf * ASZ) * 4u;
#pragma unroll
        for (int p = 0; p < 4; p++) {
            int r = lr + p * 32;
            cp16(a0 + (uint32_t)(r * (BK + PAD) + lc) * 4u,
                 &A[(long)(rowBase + r) * lda + kt + lc]);
        }
        uint32_t b0 = sB + (uint32_t)(buf * BSZ) * 4u;
        if (TRANSB) {
#pragma unroll
            for (int p = 0; p < 4; p++) {
                int n = lr + p * 32;
                cp16(b0 + (uint32_t)(n * (BK + PAD) + lc) * 4u,
                     &B[(long)(colBase + n) * ldb + kt + lc]);
            }
        } else {
#pragma unroll
            for (int p = 0; p < 4; p++) {
                int r = br + p * 8;
                cp16(b0 + (uint32_t)(r * (BN + PAD) + bc) * 4u,
                     &B[(long)(kt + r) * ldb + colBase + bc]);
            }
        }
    };

    loadStage(0, 0);
    cp_commit();

    int buf = 0;
    for (int it = 0; it < KT; it++) {
        cp_wait0();
        __syncthreads();
        if (it + 1 < KT) { loadStage((it + 1) * BK, buf ^ 1); cp_commit(); }

        const float* Ap = As + buf * ASZ;
        const float* Bp = Bs + buf * BSZ;

#pragma unroll
        for (int kk = 0; kk < BK; kk += 8) {
            wmma::fragment<wmma::matrix_a, 16, 16, 8, wmma::precision::tf32, wmma::row_major> a0, a1;
            wmma::load_matrix_sync(a0, Ap + warpRow * (BK + PAD) + kk, BK + PAD);
            wmma::load_matrix_sync(a1, Ap + (warpRow + 16) * (BK + PAD) + kk, BK + PAD);
#pragma unroll
            for (int t = 0; t < a0.num_elements; t++) {
                a0.x[t] = wmma::__float_to_tf32(a0.x[t]);
                a1.x[t] = wmma::__float_to_tf32(a1.x[t]);
            }
#pragma unroll
            for (int j = 0; j < 4; j++) {
                if constexpr (TRANSB) {
                    wmma::fragment<wmma::matrix_b, 16, 16, 8, wmma::precision::tf32, wmma::col_major> bf;
                    wmma::load_matrix_sync(bf, Bp + (warpCol + 16 * j) * (BK + PAD) + kk, BK + PAD);
#pragma unroll
                    for (int t = 0; t < bf.num_elements; t++) bf.x[t] = wmma::__float_to_tf32(bf.x[t]);
                    wmma::mma_sync(c[0][j], a0, bf, c[0][j]);
                    wmma::mma_sync(c[1][j], a1, bf, c[1][j]);
                } else {
                    wmma::fragment<wmma::matrix_b, 16, 16, 8, wmma::precision::tf32, wmma::row_major> bf;
                    wmma::load_matrix_sync(bf, Bp + kk * (BN + PAD) + warpCol + 16 * j, BN + PAD);
#pragma unroll
                    for (int t = 0; t < bf.num_elements; t++) bf.x[t] = wmma::__float_to_tf32(bf.x[t]);
                    wmma::mma_sync(c[0][j], a0, bf, c[0][j]);
                    wmma::mma_sync(c[1][j], a1, bf, c[1][j]);
                }
            }
        }
        buf ^= 1;
    }

#pragma unroll
    for (int i = 0; i < 2; i++)
#pragma unroll
        for (int j = 0; j < 4; j++)
            wmma::store_matrix_sync(
                C + (long)(rowBase + warpRow + 16 * i) * ldc + colBase + warpCol + 16 * j,
                c[i][j], ldc, wmma::mem_row_major);
}

// ---------------------------------------------------------------------------
// bias_add: C[m, n] += bias[n], N = 4096 (vectorized)
// ---------------------------------------------------------------------------
__global__ void bias_add_kernel(float* __restrict__ C, const float* __restrict__ bias)
{
    long i = ((long)blockIdx.x * blockDim.x + threadIdx.x) * 4;
    int n = (int)(i & 4095);
    float4 v = *(float4*)&C[i];
    float4 b = *(const float4*)&bias[n];
    v.x += b.x; v.y += b.y; v.z += b.z; v.w += b.w;
    *(float4*)&C[i] = v;
}

// ---------------------------------------------------------------------------
// rotary table: angles in double to exactly match numpy's float64 table.
// 16384 entries: (s, i) -> {cos, sin} at pos = MAXPOS-SEQ+s, freq i.
// ---------------------------------------------------------------------------
__global__ void rot_table_kernel()
{
    int idx = blockIdx.x * blockDim.x + threadIdx.x;
    if (idx >= SEQ * 16) return;
    int s = idx >> 4, i = idx & 15;
    const double log1e4_over16 = 0.57564627324851145;  // ln(10000)/16
    double ang = (double)(MAXPOS - SEQ + s) * exp(-(double)i * log1e4_over16);
    double sn, cs;
    sincos(ang, &sn, &cs);
    g_rot[idx] = make_float2((float)cs, (float)sn);
}

// rotary: in-place on first 32 channels of [B,S,H,HD]; one thread per (b,s,h)
__global__ void rotary_kernel(float* __restrict__ t)
{
    int idx = blockIdx.x * blockDim.x + threadIdx.x;   // 0 .. B*S*H-1
    if (idx >= BATCH * SEQ * HEADS) return;
    int s = (idx >> 5) & (SEQ - 1);
    float* ptr = t + (long)idx * HDIM;

    float x[ROTARY];
#pragma unroll
    for (int i = 0; i < ROTARY; i++) x[i] = ptr[i];

#pragma unroll
    for (int i = 0; i < 16; i++) {
        float2 cs = g_rot[s * 16 + i];
        float a = x[i], b = x[16 + i];
        ptr[2 * i]     = (float)((double)a * (double)cs.x - (double)b * (double)cs.y);
        ptr[2 * i + 1] = (float)((double)a * (double)cs.y + (double)b * (double)cs.x);
    }
}

// ---------------------------------------------------------------------------
// softmax over k (1024) per row of scores [B,H,S,S], adding scale + attn_bias.
// ---------------------------------------------------------------------------
__global__ void softmax_kernel(float* __restrict__ scores,
                               const float* __restrict__ bias, float scale)
{
    int warpsPerBlock = blockDim.x >> 5;
    long row = (long)blockIdx.x * warpsPerBlock + (threadIdx.x >> 5);
    int lane = threadIdx.x & 31;
    int q = (int)(row & (SEQ - 1));
    float* p = scores + row * SEQ;
    const float* brow = bias + (long)q * SEQ;

    float vals[32];
    float m = -1e30f;
#pragma unroll
    for (int j = 0; j < 32; j++) {
        float v = p[lane + 32 * j] * scale + brow[lane + 32 * j];
        vals[j] = v;
        m = fmaxf(m, v);
    }
#pragma unroll
    for (int o = 16; o; o >>= 1) m = fmaxf(m, __shfl_xor_sync(0xffffffffu, m, o));
    float s = 0.0f;
#pragma unroll
    for (int j = 0; j < 32; j++) { vals[j] = __expf(vals[j] - m); s += vals[j]; }
#pragma unroll
    for (int o = 16; o; o >>= 1) s += __shfl_xor_sync(0xffffffffu, s, o);
    float inv = 1.0f / s;
#pragma unroll
    for (int j = 0; j < 32; j++) p[lane + 32 * j] = vals[j] * inv;
}

// ---------------------------------------------------------------------------
extern "C" void kernel_launch(void* const* d_in, const int* in_sizes, int n_in,
                              void* d_out, int out_size)
{
    const float* x         = (const float*)d_in[0];
    const float* attn_bias = (const float*)d_in[1];
    const float* wq        = (const float*)d_in[2];
    const float* wq_b      = (const float*)d_in[3];
    const float* wk        = (const float*)d_in[4];
    const float* wk_b      = (const float*)d_in[5];
    const float* wv        = (const float*)d_in[6];
    const float* wv_b      = (const float*)d_in[7];
    const float* wo        = (const float*)d_in[8];
    const float* wo_b      = (const float*)d_in[9];
    float* out = (float*)d_out;

    float *qb, *kb, *vb, *ob, *sc;
    cudaGetSymbolAddress((void**)&qb, g_q);
    cudaGetSymbolAddress((void**)&kb, g_k);
    cudaGetSymbolAddress((void**)&vb, g_v);
    cudaGetSymbolAddress((void**)&ob, g_o);
    cudaGetSymbolAddress((void**)&sc, g_sc);

    // dynamic smem sizes
    const int smemN = (2 * BM * (BK + PAD) + 2 * BK * (BN + PAD)) * 4;  // 70656
    const int smemT = (2 * BM * (BK + PAD) + 2 * BN * (BK + PAD)) * 4;  // 73728
    cudaFuncSetAttribute(gemm_db<0>, cudaFuncAttributeMaxDynamicSharedMemorySize, smemN);
    cudaFuncSetAttribute(gemm_db<1>, cudaFuncAttributeMaxDynamicSharedMemorySize, smemT);

    dim3 blk(256);
    const long sQKV_b = (long)SEQ * HEADS * HDIM;   // 4194304
    const long sSc_b  = (long)HEADS * SEQ * SEQ;    // 33554432
    const long sSc_h  = (long)SEQ * SEQ;            // 1048576

    rot_table_kernel<<<64, 256>>>();

    // QKV projections: [4096,4096] x [4096,4096]
    gemm_db<0><<<dim3(32, 32, 1), blk, smemN>>>(x, wq, qb, 4096, 4096, 4096,
                                                4096, 4096, 4096, 0, 0, 0, 0, 0, 0, 1);
    gemm_db<0><<<dim3(32, 32, 1), blk, smemN>>>(x, wk, kb, 4096, 4096, 4096,
                                                4096, 4096, 4096, 0, 0, 0, 0, 0, 0, 1);
    gemm_db<0><<<dim3(32, 32, 1), blk, smemN>>>(x, wv, vb, 4096, 4096, 4096,
                                                4096, 4096, 4096, 0, 0, 0, 0, 0, 0, 1);

    bias_add_kernel<<<16384, 256>>>(qb, wq_b);
    bias_add_kernel<<<16384, 256>>>(kb, wk_b);
    bias_add_kernel<<<16384, 256>>>(vb, wv_b);

    rotary_kernel<<<512, 256>>>(qb);
    rotary_kernel<<<512, 256>>>(kb);

    // scores[b,h,q,k] = Q . K^T
    gemm_db<1><<<dim3(8, 8, 128), blk, smemT>>>(qb, kb, sc, 1024, 1024, 128,
                                                4096, 4096, 1024,
                                                sQKV_b, 128, sQKV_b, 128, sSc_b, sSc_h,
                                                HEADS);

    softmax_kernel<<<16384, 256>>>(sc, attn_bias, 0.08838834764831845f);

    // O[b,s,h,d] = P . V
    gemm_db<0><<<dim3(1, 8, 128), blk, smemN>>>(sc, vb, ob, 1024, 128, 1024,
                                                1024, 4096, 4096,
                                                sSc_b, sSc_h, sQKV_b, 128, sQKV_b, 128,
                                                HEADS);

    // out = O . wo + wo_bias
    gemm_db<0><<<dim3(32, 32, 1), blk, smemN>>>(ob, wo, out, 4096, 4096, 4096,
                                                4096, 4096, 4096, 0, 0, 0, 0, 0, 0, 1);
    bias_add_kernel<<<16384, 256>>>(out, wo_b);
}

// round 4
// speedup vs baseline: 1.4367x; 1.0606x over previous
#include <cuda_runtime.h>
#include <cuda_bf16.h>
#include <mma.h>
#include <cstdint>

using namespace nvcuda;

// Problem constants
#define BATCH 4
#define SEQ   1024
#define DMODEL 4096
#define HEADS 32
#define HDIM  128
#define ROTARY 32
#define MAXPOS 10000

// GEMM tiling
#define BM 128
#define BN 128
#define BK 32
#define PAD 4
#define ST 3        // pipeline stages

// Scratch (device globals; no allocation allowed)
__device__ float g_x [(long)DMODEL*DMODEL];             // tf32-rounded x
__device__ float g_wq[(long)DMODEL*DMODEL];             // tf32-rounded weights
__device__ float g_wk[(long)DMODEL*DMODEL];
__device__ float g_wv[(long)DMODEL*DMODEL];
__device__ float g_wo[(long)DMODEL*DMODEL];
__device__ float g_q [(long)BATCH*SEQ*HEADS*HDIM];      // [B,S,H,HD]
__device__ float g_k [(long)BATCH*SEQ*HEADS*HDIM];
__device__ float g_v [(long)BATCH*SEQ*HEADS*HDIM];
__device__ float g_o [(long)BATCH*SEQ*HEADS*HDIM];
__device__ float g_sc[(long)BATCH*HEADS*SEQ*SEQ];       // [B,H,S,S] 512MB
__device__ float2 g_rot[SEQ*16];

// ---------------------------------------------------------------------------
// helpers
// ---------------------------------------------------------------------------
__device__ __forceinline__ float tf32r(float v) {
    float o; asm("cvt.rna.tf32.f32 %0, %1;" : "=f"(o) : "f"(v)); return o;
}
__device__ __forceinline__ void cp16(uint32_t saddr, const float* gptr) {
    asm volatile("cp.async.cg.shared.global [%0], [%1], 16;\n" :: "r"(saddr), "l"(gptr));
}
__device__ __forceinline__ void cp_commit() { asm volatile("cp.async.commit_group;\n"); }
__device__ __forceinline__ void cp_wait1()  { asm volatile("cp.async.wait_group 1;\n"); }

// ---------------------------------------------------------------------------
// 3-stage cp.async GEMM: C[M,N] = A[M,K] * B[K,N]  (all operands pre-rounded
// to tf32, so no per-fragment conversion is needed).
//   TRANSB: logical B[k,n] = Bp[n*ldb + k].
//   ROUNDC: round C to tf32 before store (for PV output feeding next GEMM).
// ---------------------------------------------------------------------------
template<int TRANSB, int ROUNDC>
__global__ __launch_bounds__(256) void gemm_db(
    const float* __restrict__ Ab, const float* __restrict__ Bb,
    float* __restrict__ Cb,
    int M, int N, int K,
    int lda, int ldb, int ldc,
    long sAb, long sAh, long sBb, long sBh, long sCb, long sCh,
    int Hb)
{
    constexpr int ASZ = BM * (BK + PAD);                              // 4608
    constexpr int BSZ = TRANSB ? BN * (BK + PAD) : BK * (BN + PAD);   // 4608 / 4224
    extern __shared__ float sm[];
    float* As = sm;               // [ST][ASZ]
    float* Bs = sm + ST * ASZ;    // [ST][BSZ]

    int z = blockIdx.z;
    int bb = z / Hb, hh = z % Hb;
    const float* A = Ab + bb * sAb + hh * sAh;
    const float* B = Bb + bb * sBb + hh * sBh;
    float*       C = Cb + bb * sCb + hh * sCh;

    int rowBase = blockIdx.y * BM;
    int colBase = blockIdx.x * BN;

    int tid = threadIdx.x;
    int wid = tid >> 5;
    int warpRow = (wid & 3) * 32;   // 4 warps along M
    int warpCol = (wid >> 2) * 64;  // 2 warps along N

    // loader indices
    int lr = tid >> 3;          // 0..31
    int lc = (tid & 7) * 4;     // 0,4,..,28
    int br = tid >> 5;          // 0..7
    int bc = (tid & 31) * 4;    // 0..124

    uint32_t sA = (uint32_t)__cvta_generic_to_shared(As);
    uint32_t sB = (uint32_t)__cvta_generic_to_shared(Bs);

    wmma::fragment<wmma::accumulator, 16, 16, 8, float> c[2][4];
#pragma unroll
    for (int i = 0; i < 2; i++)
#pragma unroll
        for (int j = 0; j < 4; j++) wmma::fill_fragment(c[i][j], 0.0f);

    const int KT = K / BK;

    auto loadStage = [&](int kt, int buf) {
        uint32_t a0 = sA + (uint32_t)(buf * ASZ) * 4u;
#pragma unroll
        for (int p = 0; p < 4; p++) {
            int r = lr + p * 32;
            cp16(a0 + (uint32_t)(r * (BK + PAD) + lc) * 4u,
                 &A[(long)(rowBase + r) * lda + kt + lc]);
        }
        uint32_t b0 = sB + (uint32_t)(buf * BSZ) * 4u;
        if (TRANSB) {
#pragma unroll
            for (int p = 0; p < 4; p++) {
                int n = lr + p * 32;
                cp16(b0 + (uint32_t)(n * (BK + PAD) + lc) * 4u,
                     &B[(long)(colBase + n) * ldb + kt + lc]);
            }
        } else {
#pragma unroll
            for (int p = 0; p < 4; p++) {
                int r = br + p * 8;
                cp16(b0 + (uint32_t)(r * (BN + PAD) + bc) * 4u,
                     &B[(long)(kt + r) * ldb + colBase + bc]);
            }
        }
    };

    // prologue: stages 0 and 1
    loadStage(0, 0); cp_commit();
    if (1 < KT) loadStage(BK, 1);
    cp_commit();

    for (int it = 0; it < KT; it++) {
        int s = it % ST;
        cp_wait1();                // all but newest group done -> stage `it` resident
        __syncthreads();
        int nxt = it + 2;
        if (nxt < KT) loadStage(nxt * BK, nxt % ST);
        cp_commit();               // always commit to keep group accounting aligned

        const float* Ap = As + s * ASZ;
        const float* Bp = Bs + s * BSZ;

#pragma unroll
        for (int kk = 0; kk < BK; kk += 8) {
            wmma::fragment<wmma::matrix_a, 16, 16, 8, wmma::precision::tf32, wmma::row_major> a0, a1;
            wmma::load_matrix_sync(a0, Ap + warpRow * (BK + PAD) + kk, BK + PAD);
            wmma::load_matrix_sync(a1, Ap + (warpRow + 16) * (BK + PAD) + kk, BK + PAD);
#pragma unroll
            for (int j = 0; j < 4; j++) {
                if constexpr (TRANSB) {
                    wmma::fragment<wmma::matrix_b, 16, 16, 8, wmma::precision::tf32, wmma::col_major> bf;
                    wmma::load_matrix_sync(bf, Bp + (warpCol + 16 * j) * (BK + PAD) + kk, BK + PAD);
                    wmma::mma_sync(c[0][j], a0, bf, c[0][j]);
                    wmma::mma_sync(c[1][j], a1, bf, c[1][j]);
                } else {
                    wmma::fragment<wmma::matrix_b, 16, 16, 8, wmma::precision::tf32, wmma::row_major> bf;
                    wmma::load_matrix_sync(bf, Bp + kk * (BN + PAD) + warpCol + 16 * j, BN + PAD);
                    wmma::mma_sync(c[0][j], a0, bf, c[0][j]);
                    wmma::mma_sync(c[1][j], a1, bf, c[1][j]);
                }
            }
        }
    }

#pragma unroll
    for (int i = 0; i < 2; i++)
#pragma unroll
        for (int j = 0; j < 4; j++) {
            if (ROUNDC) {
#pragma unroll
                for (int t = 0; t < c[i][j].num_elements; t++)
                    c[i][j].x[t] = tf32r(c[i][j].x[t]);
            }
            wmma::store_matrix_sync(
                C + (long)(rowBase + warpRow + 16 * i) * ldc + colBase + warpCol + 16 * j,
                c[i][j], ldc, wmma::mem_row_major);
        }
}

// ---------------------------------------------------------------------------
// elementwise tf32 rounding: out[i] = round(in[i])
// ---------------------------------------------------------------------------
__global__ void round_kernel(const float* __restrict__ in, float* __restrict__ out)
{
    long i = ((long)blockIdx.x * blockDim.x + threadIdx.x) * 4;
    float4 v = *(const float4*)&in[i];
    v.x = tf32r(v.x); v.y = tf32r(v.y); v.z = tf32r(v.z); v.w = tf32r(v.w);
    *(float4*)&out[i] = v;
}

// bias add + tf32 round (for V), N = 4096
__global__ void bias_round_kernel(float* __restrict__ C, const float* __restrict__ bias)
{
    long i = ((long)blockIdx.x * blockDim.x + threadIdx.x) * 4;
    int n = (int)(i & 4095);
    float4 v = *(float4*)&C[i];
    float4 b = *(const float4*)&bias[n];
    v.x = tf32r(v.x + b.x); v.y = tf32r(v.y + b.y);
    v.z = tf32r(v.z + b.z); v.w = tf32r(v.w + b.w);
    *(float4*)&C[i] = v;
}

// plain bias add (final output), N = 4096
__global__ void bias_add_kernel(float* __restrict__ C, const float* __restrict__ bias)
{
    long i = ((long)blockIdx.x * blockDim.x + threadIdx.x) * 4;
    int n = (int)(i & 4095);
    float4 v = *(float4*)&C[i];
    float4 b = *(const float4*)&bias[n];
    v.x += b.x; v.y += b.y; v.z += b.z; v.w += b.w;
    *(float4*)&C[i] = v;
}

// ---------------------------------------------------------------------------
// rotary table (double precision, matches numpy float64)
// ---------------------------------------------------------------------------
__global__ void rot_table_kernel()
{
    int idx = blockIdx.x * blockDim.x + threadIdx.x;
    if (idx >= SEQ * 16) return;
    int s = idx >> 4, i = idx & 15;
    const double log1e4_over16 = 0.57564627324851145;  // ln(10000)/16
    double ang = (double)(MAXPOS - SEQ + s) * exp(-(double)i * log1e4_over16);
    double sn, cs;
    sincos(ang, &sn, &cs);
    g_rot[idx] = make_float2((float)cs, (float)sn);
}

// fused bias + partial rotary + tf32 round for Q/K.
// One thread per (b,s,h,quarter): quarter 0 does bias+rotary+round on ch 0..31,
// quarters 1..3 do bias+round on their 32 channels.
__global__ void bias_rot_round_kernel(float* __restrict__ t, const float* __restrict__ bias)
{
    int idx = blockIdx.x * blockDim.x + threadIdx.x;   // B*S*H*4
    int quarter = idx & 3;
    int row = idx >> 2;                                // (b*S+s)*H + h
    int h = row & (HEADS - 1);
    int s = (row >> 5) & (SEQ - 1);
    float* ptr = t + (long)row * HDIM + quarter * 32;
    const float* brow = bias + h * HDIM + quarter * 32;

    float x[32];
#pragma unroll
    for (int j = 0; j < 8; j++) {
        float4 v = *(float4*)&ptr[j * 4];
        float4 b = *(const float4*)&brow[j * 4];
        x[j*4+0] = v.x + b.x; x[j*4+1] = v.y + b.y;
        x[j*4+2] = v.z + b.z; x[j*4+3] = v.w + b.w;
    }

    if (quarter == 0) {
        float y[32];
#pragma unroll
        for (int i = 0; i < 16; i++) {
            float2 cs = g_rot[s * 16 + i];
            float a = x[i], b = x[16 + i];
            y[2*i]   = tf32r((float)((double)a * (double)cs.x - (double)b * (double)cs.y));
            y[2*i+1] = tf32r((float)((double)a * (double)cs.y + (double)b * (double)cs.x));
        }
#pragma unroll
        for (int i = 0; i < 32; i++) ptr[i] = y[i];
    } else {
#pragma unroll
        for (int i = 0; i < 32; i++) ptr[i] = tf32r(x[i]);
    }
}

// ---------------------------------------------------------------------------
// softmax over k (1024) per row, scale + attn_bias; output tf32-rounded
// ---------------------------------------------------------------------------
__global__ void softmax_kernel(float* __restrict__ scores,
                               const float* __restrict__ bias, float scale)
{
    int warpsPerBlock = blockDim.x >> 5;
    long row = (long)blockIdx.x * warpsPerBlock + (threadIdx.x >> 5);
    int lane = threadIdx.x & 31;
    int q = (int)(row & (SEQ - 1));
    float* p = scores + row * SEQ;
    const float* brow = bias + (long)q * SEQ;

    float vals[32];
    float m = -1e30f;
#pragma unroll
    for (int j = 0; j < 32; j++) {
        float v = p[lane + 32 * j] * scale + brow[lane + 32 * j];
        vals[j] = v;
        m = fmaxf(m, v);
    }
#pragma unroll
    for (int o = 16; o; o >>= 1) m = fmaxf(m, __shfl_xor_sync(0xffffffffu, m, o));
    float s = 0.0f;
#pragma unroll
    for (int j = 0; j < 32; j++) { vals[j] = __expf(vals[j] - m); s += vals[j]; }
#pragma unroll
    for (int o = 16; o; o >>= 1) s += __shfl_xor_sync(0xffffffffu, s, o);
    float inv = 1.0f / s;
#pragma unroll
    for (int j = 0; j < 32; j++) p[lane + 32 * j] = tf32r(vals[j] * inv);
}

// ---------------------------------------------------------------------------
extern "C" void kernel_launch(void* const* d_in, const int* in_sizes, int n_in,
                              void* d_out, int out_size)
{
    const float* x         = (const float*)d_in[0];
    const float* attn_bias = (const float*)d_in[1];
    const float* wq        = (const float*)d_in[2];
    const float* wq_b      = (const float*)d_in[3];
    const float* wk        = (const float*)d_in[4];
    const float* wk_b      = (const float*)d_in[5];
    const float* wv        = (const float*)d_in[6];
    const float* wv_b      = (const float*)d_in[7];
    const float* wo        = (const float*)d_in[8];
    const float* wo_b      = (const float*)d_in[9];
    float* out = (float*)d_out;

    float *xb, *wqR, *wkR, *wvR, *woR, *qb, *kb, *vb, *ob, *sc;
    cudaGetSymbolAddress((void**)&xb,  g_x);
    cudaGetSymbolAddress((void**)&wqR, g_wq);
    cudaGetSymbolAddress((void**)&wkR, g_wk);
    cudaGetSymbolAddress((void**)&wvR, g_wv);
    cudaGetSymbolAddress((void**)&woR, g_wo);
    cudaGetSymbolAddress((void**)&qb,  g_q);
    cudaGetSymbolAddress((void**)&kb,  g_k);
    cudaGetSymbolAddress((void**)&vb,  g_v);
    cudaGetSymbolAddress((void**)&ob,  g_o);
    cudaGetSymbolAddress((void**)&sc,  g_sc);

    // dynamic smem sizes
    const int smemN = (ST * BM * (BK + PAD) + ST * BK * (BN + PAD)) * 4;  // 105984
    const int smemT = (ST * BM * (BK + PAD) + ST * BN * (BK + PAD)) * 4;  // 110592
    cudaFuncSetAttribute(gemm_db<0,0>, cudaFuncAttributeMaxDynamicSharedMemorySize, smemN);
    cudaFuncSetAttribute(gemm_db<0,1>, cudaFuncAttributeMaxDynamicSharedMemorySize, smemN);
    cudaFuncSetAttribute(gemm_db<1,0>, cudaFuncAttributeMaxDynamicSharedMemorySize, smemT);

    dim3 blk(256);
    const long sQKV_b = (long)SEQ * HEADS * HDIM;   // 4194304
    const long sSc_b  = (long)HEADS * SEQ * SEQ;    // 33554432
    const long sSc_h  = (long)SEQ * SEQ;            // 1048576

    rot_table_kernel<<<64, 256>>>();

    // pre-round all GEMM operands to tf32 (RN) once
    round_kernel<<<16384, 256>>>(x,  xb);
    round_kernel<<<16384, 256>>>(wq, wqR);
    round_kernel<<<16384, 256>>>(wk, wkR);
    round_kernel<<<16384, 256>>>(wv, wvR);
    round_kernel<<<16384, 256>>>(wo, woR);

    // QKV projections: [4096,4096] x [4096,4096]
    gemm_db<0,0><<<dim3(32, 32, 1), blk, smemN>>>(xb, wqR, qb, 4096, 4096, 4096,
                                                  4096, 4096, 4096, 0, 0, 0, 0, 0, 0, 1);
    gemm_db<0,0><<<dim3(32, 32, 1), blk, smemN>>>(xb, wkR, kb, 4096, 4096, 4096,
                                                  4096, 4096, 4096, 0, 0, 0, 0, 0, 0, 1);
    gemm_db<0,0><<<dim3(32, 32, 1), blk, smemN>>>(xb, wvR, vb, 4096, 4096, 4096,
                                                  4096, 4096, 4096, 0, 0, 0, 0, 0, 0, 1);

    bias_rot_round_kernel<<<2048, 256>>>(qb, wq_b);
    bias_rot_round_kernel<<<2048, 256>>>(kb, wk_b);
    bias_round_kernel<<<16384, 256>>>(vb, wv_b);

    // scores[b,h,q,k] = Q . K^T
    gemm_db<1,0><<<dim3(8, 8, 128), blk, smemT>>>(qb, kb, sc, 1024, 1024, 128,
                                                  4096, 4096, 1024,
                                                  sQKV_b, 128, sQKV_b, 128, sSc_b, sSc_h,
                                                  HEADS);

    softmax_kernel<<<16384, 256>>>(sc, attn_bias, 0.08838834764831845f);

    // O[b,s,h,d] = P . V   (round output for the final GEMM)
    gemm_db<0,1><<<dim3(1, 8, 128), blk, smemN>>>(sc, vb, ob, 1024, 128, 1024,
                                                  1024, 4096, 4096,
                                                  sSc_b, sSc_h, sQKV_b, 128, sQKV_b, 128,
                                                  HEADS);

    // out = O . wo + wo_bias
    gemm_db<0,0><<<dim3(32, 32, 1), blk, smemN>>>(ob, woR, out, 4096, 4096, 4096,
                                                  4096, 4096, 4096, 0, 0, 0, 0, 0, 0, 1);
    bias_add_kernel<<<16384, 256>>>(out, wo_b);
}

// round 5
// speedup vs baseline: 1.5599x; 1.0858x over previous
#include <cuda_runtime.h>
#include <cuda_bf16.h>
#include <mma.h>
#include <cstdint>

using namespace nvcuda;

// Problem constants
#define BATCH 4
#define SEQ   1024
#define DMODEL 4096
#define HEADS 32
#define HDIM  128
#define ROTARY 32
#define MAXPOS 10000

// GEMM tiling
#define BM 128
#define BN 128
#define BK 32
#define PAD 4
#define ST 3        // pipeline stages

// Scratch (device globals; no allocation allowed)
__device__ float g_x [(long)DMODEL*DMODEL];             // tf32-rounded x
__device__ float g_wq[(long)DMODEL*DMODEL];             // tf32-rounded weights
__device__ float g_wk[(long)DMODEL*DMODEL];
__device__ float g_wv[(long)DMODEL*DMODEL];
__device__ float g_wo[(long)DMODEL*DMODEL];
__device__ float g_q [(long)BATCH*SEQ*HEADS*HDIM];      // [B,S,H,HD]
__device__ float g_k [(long)BATCH*SEQ*HEADS*HDIM];
__device__ float g_v [(long)BATCH*SEQ*HEADS*HDIM];
__device__ float g_o [(long)BATCH*SEQ*HEADS*HDIM];
__device__ float g_sc[(long)BATCH*HEADS*SEQ*SEQ];       // [B,H,S,S] 512MB
__device__ float2 g_rot[SEQ*16];

// ---------------------------------------------------------------------------
// helpers
// ---------------------------------------------------------------------------
__device__ __forceinline__ float tf32r(float v) {
    float o; asm("cvt.rna.tf32.f32 %0, %1;" : "=f"(o) : "f"(v)); return o;
}
__device__ __forceinline__ void cp16(uint32_t saddr, const float* gptr) {
    asm volatile("cp.async.cg.shared.global [%0], [%1], 16;\n" :: "r"(saddr), "l"(gptr));
}
__device__ __forceinline__ void cp_commit() { asm volatile("cp.async.commit_group;\n"); }
__device__ __forceinline__ void cp_wait1()  { asm volatile("cp.async.wait_group 1;\n"); }

// ---------------------------------------------------------------------------
// 3-stage cp.async GEMM: C[M,N] = A[M,K] * B[K,N]  (operands pre-rounded to
// tf32). 2 CTAs/SM via __launch_bounds__(256,2) — 4 warps/SMSP so smem-load
// and barrier latency is covered by the co-resident CTA.
//   TRANSB: logical B[k,n] = Bp[n*ldb + k].
//   ROUNDC: round C to tf32 before store.
// ---------------------------------------------------------------------------
template<int TRANSB, int ROUNDC>
__global__ __launch_bounds__(256, 2) void gemm_db(
    const float* __restrict__ Ab, const float* __restrict__ Bb,
    float* __restrict__ Cb,
    int M, int N, int K,
    int lda, int ldb, int ldc,
    long sAb, long sAh, long sBb, long sBh, long sCb, long sCh,
    int Hb)
{
    constexpr int ASZ = BM * (BK + PAD);                              // 4608
    constexpr int BSZ = TRANSB ? BN * (BK + PAD) : BK * (BN + PAD);   // 4608 / 4224
    extern __shared__ float sm[];
    float* As = sm;               // [ST][ASZ]
    float* Bs = sm + ST * ASZ;    // [ST][BSZ]

    int z = blockIdx.z;
    int bb = z / Hb, hh = z % Hb;
    const float* A = Ab + bb * sAb + hh * sAh;
    const float* B = Bb + bb * sBb + hh * sBh;
    float*       C = Cb + bb * sCb + hh * sCh;

    int rowBase = blockIdx.y * BM;
    int colBase = blockIdx.x * BN;

    int tid = threadIdx.x;
    int wid = tid >> 5;
    int warpRow = (wid & 3) * 32;   // 4 warps along M
    int warpCol = (wid >> 2) * 64;  // 2 warps along N

    // loader indices
    int lr = tid >> 3;          // 0..31
    int lc = (tid & 7) * 4;     // 0,4,..,28
    int br = tid >> 5;          // 0..7
    int bc = (tid & 31) * 4;    // 0..124

    uint32_t sA = (uint32_t)__cvta_generic_to_shared(As);
    uint32_t sB = (uint32_t)__cvta_generic_to_shared(Bs);

    wmma::fragment<wmma::accumulator, 16, 16, 8, float> c[2][4];
#pragma unroll
    for (int i = 0; i < 2; i++)
#pragma unroll
        for (int j = 0; j < 4; j++) wmma::fill_fragment(c[i][j], 0.0f);

    const int KT = K / BK;

    auto loadStage = [&](int kt, int buf) {
        uint32_t a0 = sA + (uint32_t)(buf * ASZ) * 4u;
#pragma unroll
        for (int p = 0; p < 4; p++) {
            int r = lr + p * 32;
            cp16(a0 + (uint32_t)(r * (BK + PAD) + lc) * 4u,
                 &A[(long)(rowBase + r) * lda + kt + lc]);
        }
        uint32_t b0 = sB + (uint32_t)(buf * BSZ) * 4u;
        if (TRANSB) {
#pragma unroll
            for (int p = 0; p < 4; p++) {
                int n = lr + p * 32;
                cp16(b0 + (uint32_t)(n * (BK + PAD) + lc) * 4u,
                     &B[(long)(colBase + n) * ldb + kt + lc]);
            }
        } else {
#pragma unroll
            for (int p = 0; p < 4; p++) {
                int r = br + p * 8;
                cp16(b0 + (uint32_t)(r * (BN + PAD) + bc) * 4u,
                     &B[(long)(kt + r) * ldb + colBase + bc]);
            }
        }
    };

    // prologue: stages 0 and 1
    loadStage(0, 0); cp_commit();
    if (1 < KT) loadStage(BK, 1);
    cp_commit();

    for (int it = 0; it < KT; it++) {
        int s = it % ST;
        cp_wait1();                // all but newest group done -> stage `it` resident
        __syncthreads();
        int nxt = it + 2;
        if (nxt < KT) loadStage(nxt * BK, nxt % ST);
        cp_commit();               // always commit to keep group accounting aligned

        const float* Ap = As + s * ASZ;
        const float* Bp = Bs + s * BSZ;

#pragma unroll
        for (int kk = 0; kk < BK; kk += 8) {
            wmma::fragment<wmma::matrix_a, 16, 16, 8, wmma::precision::tf32, wmma::row_major> a0, a1;
            wmma::load_matrix_sync(a0, Ap + warpRow * (BK + PAD) + kk, BK + PAD);
            wmma::load_matrix_sync(a1, Ap + (warpRow + 16) * (BK + PAD) + kk, BK + PAD);
#pragma unroll
            for (int j = 0; j < 4; j++) {
                if constexpr (TRANSB) {
                    wmma::fragment<wmma::matrix_b, 16, 16, 8, wmma::precision::tf32, wmma::col_major> bf;
                    wmma::load_matrix_sync(bf, Bp + (warpCol + 16 * j) * (BK + PAD) + kk, BK + PAD);
                    wmma::mma_sync(c[0][j], a0, bf, c[0][j]);
                    wmma::mma_sync(c[1][j], a1, bf, c[1][j]);
                } else {
                    wmma::fragment<wmma::matrix_b, 16, 16, 8, wmma::precision::tf32, wmma::row_major> bf;
                    wmma::load_matrix_sync(bf, Bp + kk * (BN + PAD) + warpCol + 16 * j, BN + PAD);
                    wmma::mma_sync(c[0][j], a0, bf, c[0][j]);
                    wmma::mma_sync(c[1][j], a1, bf, c[1][j]);
                }
            }
        }
    }

#pragma unroll
    for (int i = 0; i < 2; i++)
#pragma unroll
        for (int j = 0; j < 4; j++) {
            if (ROUNDC) {
#pragma unroll
                for (int t = 0; t < c[i][j].num_elements; t++)
                    c[i][j].x[t] = tf32r(c[i][j].x[t]);
            }
            wmma::store_matrix_sync(
                C + (long)(rowBase + warpRow + 16 * i) * ldc + colBase + warpCol + 16 * j,
                c[i][j], ldc, wmma::mem_row_major);
        }
}

// ---------------------------------------------------------------------------
// elementwise tf32 rounding: out[i] = round(in[i])
// ---------------------------------------------------------------------------
__global__ void round_kernel(const float* __restrict__ in, float* __restrict__ out)
{
    long i = ((long)blockIdx.x * blockDim.x + threadIdx.x) * 4;
    float4 v = *(const float4*)&in[i];
    v.x = tf32r(v.x); v.y = tf32r(v.y); v.z = tf32r(v.z); v.w = tf32r(v.w);
    *(float4*)&out[i] = v;
}

// bias add + tf32 round (for V), N = 4096
__global__ void bias_round_kernel(float* __restrict__ C, const float* __restrict__ bias)
{
    long i = ((long)blockIdx.x * blockDim.x + threadIdx.x) * 4;
    int n = (int)(i & 4095);
    float4 v = *(float4*)&C[i];
    float4 b = *(const float4*)&bias[n];
    v.x = tf32r(v.x + b.x); v.y = tf32r(v.y + b.y);
    v.z = tf32r(v.z + b.z); v.w = tf32r(v.w + b.w);
    *(float4*)&C[i] = v;
}

// plain bias add (final output), N = 4096
__global__ void bias_add_kernel(float* __restrict__ C, const float* __restrict__ bias)
{
    long i = ((long)blockIdx.x * blockDim.x + threadIdx.x) * 4;
    int n = (int)(i & 4095);
    float4 v = *(float4*)&C[i];
    float4 b = *(const float4*)&bias[n];
    v.x += b.x; v.y += b.y; v.z += b.z; v.w += b.w;
    *(float4*)&C[i] = v;
}

// ---------------------------------------------------------------------------
// rotary table (double precision, matches numpy float64)
// ---------------------------------------------------------------------------
__global__ void rot_table_kernel()
{
    int idx = blockIdx.x * blockDim.x + threadIdx.x;
    if (idx >= SEQ * 16) return;
    int s = idx >> 4, i = idx & 15;
    const double log1e4_over16 = 0.57564627324851145;  // ln(10000)/16
    double ang = (double)(MAXPOS - SEQ + s) * exp(-(double)i * log1e4_over16);
    double sn, cs;
    sincos(ang, &sn, &cs);
    g_rot[idx] = make_float2((float)cs, (float)sn);
}

// fused bias + partial rotary + tf32 round for Q/K.
// One thread per (b,s,h,quarter): quarter 0 does bias+rotary+round on ch 0..31,
// quarters 1..3 do bias+round on their 32 channels.
__global__ void bias_rot_round_kernel(float* __restrict__ t, const float* __restrict__ bias)
{
    int idx = blockIdx.x * blockDim.x + threadIdx.x;   // B*S*H*4
    int quarter = idx & 3;
    int row = idx >> 2;                                // (b*S+s)*H + h
    int h = row & (HEADS - 1);
    int s = (row >> 5) & (SEQ - 1);
    float* ptr = t + (long)row * HDIM + quarter * 32;
    const float* brow = bias + h * HDIM + quarter * 32;

    float x[32];
#pragma unroll
    for (int j = 0; j < 8; j++) {
        float4 v = *(float4*)&ptr[j * 4];
        float4 b = *(const float4*)&brow[j * 4];
        x[j*4+0] = v.x + b.x; x[j*4+1] = v.y + b.y;
        x[j*4+2] = v.z + b.z; x[j*4+3] = v.w + b.w;
    }

    if (quarter == 0) {
        float y[32];
#pragma unroll
        for (int i = 0; i < 16; i++) {
            float2 cs = g_rot[s * 16 + i];
            float a = x[i], b = x[16 + i];
            y[2*i]   = tf32r((float)((double)a * (double)cs.x - (double)b * (double)cs.y));
            y[2*i+1] = tf32r((float)((double)a * (double)cs.y + (double)b * (double)cs.x));
        }
#pragma unroll
        for (int i = 0; i < 32; i++) ptr[i] = y[i];
    } else {
#pragma unroll
        for (int i = 0; i < 32; i++) ptr[i] = tf32r(x[i]);
    }
}

// ---------------------------------------------------------------------------
// softmax over k (1024) per row, scale + attn_bias; output tf32-rounded
// ---------------------------------------------------------------------------
__global__ void softmax_kernel(float* __restrict__ scores,
                               const float* __restrict__ bias, float scale)
{
    int warpsPerBlock = blockDim.x >> 5;
    long row = (long)blockIdx.x * warpsPerBlock + (threadIdx.x >> 5);
    int lane = threadIdx.x & 31;
    int q = (int)(row & (SEQ - 1));
    float* p = scores + row * SEQ;
    const float* brow = bias + (long)q * SEQ;

    float vals[32];
    float m = -1e30f;
#pragma unroll
    for (int j = 0; j < 32; j++) {
        float v = p[lane + 32 * j] * scale + brow[lane + 32 * j];
        vals[j] = v;
        m = fmaxf(m, v);
    }
#pragma unroll
    for (int o = 16; o; o >>= 1) m = fmaxf(m, __shfl_xor_sync(0xffffffffu, m, o));
    float s = 0.0f;
#pragma unroll
    for (int j = 0; j < 32; j++) { vals[j] = __expf(vals[j] - m); s += vals[j]; }
#pragma unroll
    for (int o = 16; o; o >>= 1) s += __shfl_xor_sync(0xffffffffu, s, o);
    float inv = 1.0f / s;
#pragma unroll
    for (int j = 0; j < 32; j++) p[lane + 32 * j] = tf32r(vals[j] * inv);
}

// ---------------------------------------------------------------------------
extern "C" void kernel_launch(void* const* d_in, const int* in_sizes, int n_in,
                              void* d_out, int out_size)
{
    const float* x         = (const float*)d_in[0];
    const float* attn_bias = (const float*)d_in[1];
    const float* wq        = (const float*)d_in[2];
    const float* wq_b      = (const float*)d_in[3];
    const float* wk        = (const float*)d_in[4];
    const float* wk_b      = (const float*)d_in[5];
    const float* wv        = (const float*)d_in[6];
    const float* wv_b      = (const float*)d_in[7];
    const float* wo        = (const float*)d_in[8];
    const float* wo_b      = (const float*)d_in[9];
    float* out = (float*)d_out;

    float *xb, *wqR, *wkR, *wvR, *woR, *qb, *kb, *vb, *ob, *sc;
    cudaGetSymbolAddress((void**)&xb,  g_x);
    cudaGetSymbolAddress((void**)&wqR, g_wq);
    cudaGetSymbolAddress((void**)&wkR, g_wk);
    cudaGetSymbolAddress((void**)&wvR, g_wv);
    cudaGetSymbolAddress((void**)&woR, g_wo);
    cudaGetSymbolAddress((void**)&qb,  g_q);
    cudaGetSymbolAddress((void**)&kb,  g_k);
    cudaGetSymbolAddress((void**)&vb,  g_v);
    cudaGetSymbolAddress((void**)&ob,  g_o);
    cudaGetSymbolAddress((void**)&sc,  g_sc);

    // dynamic smem sizes
    const int smemN = (ST * BM * (BK + PAD) + ST * BK * (BN + PAD)) * 4;  // 105984
    const int smemT = (ST * BM * (BK + PAD) + ST * BN * (BK + PAD)) * 4;  // 110592
    cudaFuncSetAttribute(gemm_db<0,0>, cudaFuncAttributeMaxDynamicSharedMemorySize, smemN);
    cudaFuncSetAttribute(gemm_db<0,1>, cudaFuncAttributeMaxDynamicSharedMemorySize, smemN);
    cudaFuncSetAttribute(gemm_db<1,0>, cudaFuncAttributeMaxDynamicSharedMemorySize, smemT);

    dim3 blk(256);
    const long sQKV_b = (long)SEQ * HEADS * HDIM;   // 4194304
    const long sSc_b  = (long)HEADS * SEQ * SEQ;    // 33554432
    const long sSc_h  = (long)SEQ * SEQ;            // 1048576

    rot_table_kernel<<<64, 256>>>();

    // pre-round all GEMM operands to tf32 (RN) once
    round_kernel<<<16384, 256>>>(x,  xb);
    round_kernel<<<16384, 256>>>(wq, wqR);
    round_kernel<<<16384, 256>>>(wk, wkR);
    round_kernel<<<16384, 256>>>(wv, wvR);
    round_kernel<<<16384, 256>>>(wo, woR);

    // QKV projections: [4096,4096] x [4096,4096]
    gemm_db<0,0><<<dim3(32, 32, 1), blk, smemN>>>(xb, wqR, qb, 4096, 4096, 4096,
                                                  4096, 4096, 4096, 0, 0, 0, 0, 0, 0, 1);
    gemm_db<0,0><<<dim3(32, 32, 1), blk, smemN>>>(xb, wkR, kb, 4096, 4096, 4096,
                                                  4096, 4096, 4096, 0, 0, 0, 0, 0, 0, 1);
    gemm_db<0,0><<<dim3(32, 32, 1), blk, smemN>>>(xb, wvR, vb, 4096, 4096, 4096,
                                                  4096, 4096, 4096, 0, 0, 0, 0, 0, 0, 1);

    bias_rot_round_kernel<<<2048, 256>>>(qb, wq_b);
    bias_rot_round_kernel<<<2048, 256>>>(kb, wk_b);
    bias_round_kernel<<<16384, 256>>>(vb, wv_b);

    // scores[b,h,q,k] = Q . K^T
    gemm_db<1,0><<<dim3(8, 8, 128), blk, smemT>>>(qb, kb, sc, 1024, 1024, 128,
                                                  4096, 4096, 1024,
                                                  sQKV_b, 128, sQKV_b, 128, sSc_b, sSc_h,
                                                  HEADS);

    softmax_kernel<<<16384, 256>>>(sc, attn_bias, 0.08838834764831845f);

    // O[b,s,h,d] = P . V   (round output for the final GEMM)
    gemm_db<0,1><<<dim3(1, 8, 128), blk, smemN>>>(sc, vb, ob, 1024, 128, 1024,
                                                  1024, 4096, 4096,
                                                  sSc_b, sSc_h, sQKV_b, 128, sQKV_b, 128,
                                                  HEADS);

    // out = O . wo + wo_bias
    gemm_db<0,0><<<dim3(32, 32, 1), blk, smemN>>>(ob, woR, out, 4096, 4096, 4096,
                                                  4096, 4096, 4096, 0, 0, 0, 0, 0, 0, 1);
    bias_add_kernel<<<16384, 256>>>(out, wo_b);
}

// round 6
// speedup vs baseline: 5.5967x; 3.5878x over previous
#include <cuda_runtime.h>
#include <cuda_fp16.h>
#include <mma.h>
#include <cstdint>

using namespace nvcuda;

// Problem constants
#define BATCH 4
#define SEQ   1024
#define DMODEL 4096
#define HEADS 32
#define HDIM  128
#define ROTARY 32
#define MAXPOS 10000

// GEMM tiling (fp16 operands, fp32 accum)
#define BM 128
#define BN 128
#define BK 64
#define PADH 8      // 8 halfs = 16B pad
#define ST 3        // pipeline stages

// Scratch (device globals; no allocation allowed)
__device__ __half g_xh [(long)DMODEL*DMODEL];           // fp16 x
__device__ __half g_wqh[(long)DMODEL*DMODEL];           // fp16 weights
__device__ __half g_wkh[(long)DMODEL*DMODEL];
__device__ __half g_wvh[(long)DMODEL*DMODEL];
__device__ __half g_woh[(long)DMODEL*DMODEL];
__device__ float  g_f  [(long)BATCH*SEQ*HEADS*HDIM];    // fp32 GEMM out scratch (reused)
__device__ __half g_qh [(long)BATCH*SEQ*HEADS*HDIM];    // fp16 q (post bias+rotary)
__device__ __half g_kh [(long)BATCH*SEQ*HEADS*HDIM];
__device__ __half g_vh [(long)BATCH*SEQ*HEADS*HDIM];
__device__ __half g_oh [(long)BATCH*SEQ*HEADS*HDIM];
__device__ float  g_sc [(long)BATCH*HEADS*SEQ*SEQ];     // fp32 scores 512MB
__device__ __half g_ph [(long)BATCH*HEADS*SEQ*SEQ];     // fp16 probs 256MB
__device__ float2 g_rot[SEQ*16];

// ---------------------------------------------------------------------------
// helpers
// ---------------------------------------------------------------------------
__device__ __forceinline__ void cp16(uint32_t saddr, const void* gptr) {
    asm volatile("cp.async.cg.shared.global [%0], [%1], 16;\n" :: "r"(saddr), "l"(gptr));
}
__device__ __forceinline__ void cp_commit() { asm volatile("cp.async.commit_group;\n"); }
__device__ __forceinline__ void cp_wait1()  { asm volatile("cp.async.wait_group 1;\n"); }

// ---------------------------------------------------------------------------
// fp16 GEMM, fp32 accumulate: C[M,N] = A[M,K] * B[K,N]
//   TRANSB: logical B[k,n] = Bp[n*ldb + k]  (col-major fragments)
//   3-stage cp.async pipeline, BK=64, 2 CTAs/SM.
// ---------------------------------------------------------------------------
template<int TRANSB>
__global__ __launch_bounds__(256, 2) void gemm_h(
    const __half* __restrict__ Ab, const __half* __restrict__ Bb,
    float* __restrict__ Cb,
    int lda, int ldb, int ldc,
    long sAb, long sAh, long sBb, long sBh, long sCb, long sCh,
    int Hb, int KT)
{
    constexpr int ASZ = BM * (BK + PADH);                               // 9216 halfs
    constexpr int BSZ = TRANSB ? BN * (BK + PADH) : BK * (BN + PADH);   // 9216 / 8704
    extern __shared__ __half smh[];
    __half* As = smh;              // [ST][ASZ]
    __half* Bs = smh + ST * ASZ;   // [ST][BSZ]

    int z = blockIdx.z;
    int bb = z / Hb, hh = z % Hb;
    const __half* A = Ab + bb * sAb + hh * sAh;
    const __half* B = Bb + bb * sBb + hh * sBh;
    float*        C = Cb + bb * sCb + hh * sCh;

    int rowBase = blockIdx.y * BM;
    int colBase = blockIdx.x * BN;

    int tid = threadIdx.x;
    int wid = tid >> 5;
    int warpRow = (wid & 3) * 32;   // 4 warps along M
    int warpCol = (wid >> 2) * 64;  // 2 warps along N

    // loader indices: A / B-trans tiles are 128 rows x 64 halfs (8 chunks/row)
    int lr = tid >> 3;           // 0..31
    int lc = (tid & 7) * 8;      // 0,8,..,56 (halfs)
    // B normal tile: 64 rows x 128 halfs (16 chunks/row)
    int br = tid >> 4;           // 0..15
    int bc = (tid & 15) * 8;     // 0..120 (halfs)

    uint32_t sA = (uint32_t)__cvta_generic_to_shared(As);
    uint32_t sB = (uint32_t)__cvta_generic_to_shared(Bs);

    wmma::fragment<wmma::accumulator, 16, 16, 16, float> c[2][4];
#pragma unroll
    for (int i = 0; i < 2; i++)
#pragma unroll
        for (int j = 0; j < 4; j++) wmma::fill_fragment(c[i][j], 0.0f);

    auto loadStage = [&](int kt, int buf) {
        uint32_t a0 = sA + (uint32_t)(buf * ASZ) * 2u;
#pragma unroll
        for (int p = 0; p < 4; p++) {
            int r = lr + p * 32;
            cp16(a0 + (uint32_t)(r * (BK + PADH) + lc) * 2u,
                 &A[(long)(rowBase + r) * lda + kt + lc]);
        }
        uint32_t b0 = sB + (uint32_t)(buf * BSZ) * 2u;
        if (TRANSB) {
#pragma unroll
            for (int p = 0; p < 4; p++) {
                int n = lr + p * 32;
                cp16(b0 + (uint32_t)(n * (BK + PADH) + lc) * 2u,
                     &B[(long)(colBase + n) * ldb + kt + lc]);
            }
        } else {
#pragma unroll
            for (int p = 0; p < 4; p++) {
                int r = br + p * 16;
                cp16(b0 + (uint32_t)(r * (BN + PADH) + bc) * 2u,
                     &B[(long)(kt + r) * ldb + colBase + bc]);
            }
        }
    };

    // prologue: stages 0 and 1
    loadStage(0, 0); cp_commit();
    if (1 < KT) loadStage(BK, 1);
    cp_commit();

    for (int it = 0; it < KT; it++) {
        int s = it % ST;
        cp_wait1();                // stage `it` resident
        __syncthreads();
        int nxt = it + 2;
        if (nxt < KT) loadStage(nxt * BK, nxt % ST);
        cp_commit();               // keep group accounting aligned

        const __half* Ap = As + s * ASZ;
        const __half* Bp = Bs + s * BSZ;

#pragma unroll
        for (int kk = 0; kk < BK; kk += 16) {
            wmma::fragment<wmma::matrix_a, 16, 16, 16, __half, wmma::row_major> a0, a1;
            wmma::load_matrix_sync(a0, Ap + warpRow * (BK + PADH) + kk, BK + PADH);
            wmma::load_matrix_sync(a1, Ap + (warpRow + 16) * (BK + PADH) + kk, BK + PADH);
#pragma unroll
            for (int j = 0; j < 4; j++) {
                if constexpr (TRANSB) {
                    wmma::fragment<wmma::matrix_b, 16, 16, 16, __half, wmma::col_major> bf;
                    wmma::load_matrix_sync(bf, Bp + (warpCol + 16 * j) * (BK + PADH) + kk, BK + PADH);
                    wmma::mma_sync(c[0][j], a0, bf, c[0][j]);
                    wmma::mma_sync(c[1][j], a1, bf, c[1][j]);
                } else {
                    wmma::fragment<wmma::matrix_b, 16, 16, 16, __half, wmma::row_major> bf;
                    wmma::load_matrix_sync(bf, Bp + kk * (BN + PADH) + warpCol + 16 * j, BN + PADH);
                    wmma::mma_sync(c[0][j], a0, bf, c[0][j]);
                    wmma::mma_sync(c[1][j], a1, bf, c[1][j]);
                }
            }
        }
    }

#pragma unroll
    for (int i = 0; i < 2; i++)
#pragma unroll
        for (int j = 0; j < 4; j++)
            wmma::store_matrix_sync(
                C + (long)(rowBase + warpRow + 16 * i) * ldc + colBase + warpCol + 16 * j,
                c[i][j], ldc, wmma::mem_row_major);
}

// ---------------------------------------------------------------------------
// f32 -> f16 convert (RN), 8 elems/thread
// ---------------------------------------------------------------------------
__global__ void f2h_kernel(const float* __restrict__ in, __half* __restrict__ out)
{
    long i = ((long)blockIdx.x * blockDim.x + threadIdx.x) * 8;
    float4 a = *(const float4*)&in[i];
    float4 b = *(const float4*)&in[i + 4];
    __half2 h0 = __floats2half2_rn(a.x, a.y);
    __half2 h1 = __floats2half2_rn(a.z, a.w);
    __half2 h2 = __floats2half2_rn(b.x, b.y);
    __half2 h3 = __floats2half2_rn(b.z, b.w);
    uint4 o;
    o.x = *(uint32_t*)&h0; o.y = *(uint32_t*)&h1;
    o.z = *(uint32_t*)&h2; o.w = *(uint32_t*)&h3;
    *(uint4*)&out[i] = o;
}

// bias add (fp32) then f16 convert, N = 4096 (for V)
__global__ void bias_f2h_kernel(const float* __restrict__ in,
                                const float* __restrict__ bias,
                                __half* __restrict__ out)
{
    long i = ((long)blockIdx.x * blockDim.x + threadIdx.x) * 4;
    int n = (int)(i & 4095);
    float4 v = *(const float4*)&in[i];
    float4 b = *(const float4*)&bias[n];
    __half2 h0 = __floats2half2_rn(v.x + b.x, v.y + b.y);
    __half2 h1 = __floats2half2_rn(v.z + b.z, v.w + b.w);
    uint2 o; o.x = *(uint32_t*)&h0; o.y = *(uint32_t*)&h1;
    *(uint2*)&out[i] = o;
}

// plain bias add fp32 (final output), N = 4096
__global__ void bias_add_kernel(float* __restrict__ C, const float* __restrict__ bias)
{
    long i = ((long)blockIdx.x * blockDim.x + threadIdx.x) * 4;
    int n = (int)(i & 4095);
    float4 v = *(float4*)&C[i];
    float4 b = *(const float4*)&bias[n];
    v.x += b.x; v.y += b.y; v.z += b.z; v.w += b.w;
    *(float4*)&C[i] = v;
}

// ---------------------------------------------------------------------------
// rotary table (double precision, matches numpy float64)
// ---------------------------------------------------------------------------
__global__ void rot_table_kernel()
{
    int idx = blockIdx.x * blockDim.x + threadIdx.x;
    if (idx >= SEQ * 16) return;
    int s = idx >> 4, i = idx & 15;
    const double log1e4_over16 = 0.57564627324851145;  // ln(10000)/16
    double ang = (double)(MAXPOS - SEQ + s) * exp(-(double)i * log1e4_over16);
    double sn, cs;
    sincos(ang, &sn, &cs);
    g_rot[idx] = make_float2((float)cs, (float)sn);
}

// fused bias + partial rotary + f16 convert for Q/K (fp32 in, f16 out).
// One thread per (b,s,h,quarter): quarter 0 = bias+rotary+convert on ch 0..31,
// quarters 1..3 = bias+convert.
__global__ void bias_rot_h_kernel(const float* __restrict__ t,
                                  const float* __restrict__ bias,
                                  __half* __restrict__ out)
{
    int idx = blockIdx.x * blockDim.x + threadIdx.x;   // B*S*H*4
    int quarter = idx & 3;
    int row = idx >> 2;                                // (b*S+s)*H + h
    int h = row & (HEADS - 1);
    int s = (row >> 5) & (SEQ - 1);
    const float* ptr = t + (long)row * HDIM + quarter * 32;
    const float* brow = bias + h * HDIM + quarter * 32;
    __half* optr = out + (long)row * HDIM + quarter * 32;

    float x[32];
#pragma unroll
    for (int j = 0; j < 8; j++) {
        float4 v = *(const float4*)&ptr[j * 4];
        float4 b = *(const float4*)&brow[j * 4];
        x[j*4+0] = v.x + b.x; x[j*4+1] = v.y + b.y;
        x[j*4+2] = v.z + b.z; x[j*4+3] = v.w + b.w;
    }

    if (quarter == 0) {
        float y[32];
#pragma unroll
        for (int i = 0; i < 16; i++) {
            float2 cs = g_rot[s * 16 + i];
            float a = x[i], b = x[16 + i];
            y[2*i]   = (float)((double)a * (double)cs.x - (double)b * (double)cs.y);
            y[2*i+1] = (float)((double)a * (double)cs.y + (double)b * (double)cs.x);
        }
#pragma unroll
        for (int i = 0; i < 16; i++) {
            __half2 hh = __floats2half2_rn(y[2*i], y[2*i+1]);
            *(uint32_t*)&optr[2*i] = *(uint32_t*)&hh;
        }
    } else {
#pragma unroll
        for (int i = 0; i < 16; i++) {
            __half2 hh = __floats2half2_rn(x[2*i], x[2*i+1]);
            *(uint32_t*)&optr[2*i] = *(uint32_t*)&hh;
        }
    }
}

// ---------------------------------------------------------------------------
// softmax over k (1024) per row, scale + attn_bias; fp32 in, fp16 out
// ---------------------------------------------------------------------------
__global__ void softmax_kernel(const float* __restrict__ scores,
                               const float* __restrict__ bias,
                               __half* __restrict__ probs, float scale)
{
    int warpsPerBlock = blockDim.x >> 5;
    long row = (long)blockIdx.x * warpsPerBlock + (threadIdx.x >> 5);
    int lane = threadIdx.x & 31;
    int q = (int)(row & (SEQ - 1));
    const float* p = scores + row * SEQ;
    const float* brow = bias + (long)q * SEQ;
    __half* po = probs + row * SEQ;

    float vals[32];
    float m = -1e30f;
#pragma unroll
    for (int j = 0; j < 32; j++) {
        float v = p[lane + 32 * j] * scale + brow[lane + 32 * j];
        vals[j] = v;
        m = fmaxf(m, v);
    }
#pragma unroll
    for (int o = 16; o; o >>= 1) m = fmaxf(m, __shfl_xor_sync(0xffffffffu, m, o));
    float s = 0.0f;
#pragma unroll
    for (int j = 0; j < 32; j++) { vals[j] = __expf(vals[j] - m); s += vals[j]; }
#pragma unroll
    for (int o = 16; o; o >>= 1) s += __shfl_xor_sync(0xffffffffu, s, o);
    float inv = 1.0f / s;
#pragma unroll
    for (int j = 0; j < 32; j++) po[lane + 32 * j] = __float2half_rn(vals[j] * inv);
}

// ---------------------------------------------------------------------------
extern "C" void kernel_launch(void* const* d_in, const int* in_sizes, int n_in,
                              void* d_out, int out_size)
{
    const float* x         = (const float*)d_in[0];
    const float* attn_bias = (const float*)d_in[1];
    const float* wq        = (const float*)d_in[2];
    const float* wq_b      = (const float*)d_in[3];
    const float* wk        = (const float*)d_in[4];
    const float* wk_b      = (const float*)d_in[5];
    const float* wv        = (const float*)d_in[6];
    const float* wv_b      = (const float*)d_in[7];
    const float* wo        = (const float*)d_in[8];
    const float* wo_b      = (const float*)d_in[9];
    float* out = (float*)d_out;

    __half *xh, *wqh, *wkh, *wvh, *woh, *qh, *kh, *vh, *oh, *ph;
    float *fb, *sc;
    cudaGetSymbolAddress((void**)&xh,  g_xh);
    cudaGetSymbolAddress((void**)&wqh, g_wqh);
    cudaGetSymbolAddress((void**)&wkh, g_wkh);
    cudaGetSymbolAddress((void**)&wvh, g_wvh);
    cudaGetSymbolAddress((void**)&woh, g_woh);
    cudaGetSymbolAddress((void**)&fb,  g_f);
    cudaGetSymbolAddress((void**)&qh,  g_qh);
    cudaGetSymbolAddress((void**)&kh,  g_kh);
    cudaGetSymbolAddress((void**)&vh,  g_vh);
    cudaGetSymbolAddress((void**)&oh,  g_oh);
    cudaGetSymbolAddress((void**)&sc,  g_sc);
    cudaGetSymbolAddress((void**)&ph,  g_ph);

    // dynamic smem (bytes)
    const int smemN = (ST * BM * (BK + PADH) + ST * BK * (BN + PADH)) * 2;  // 107520
    const int smemT = (ST * BM * (BK + PADH) + ST * BN * (BK + PADH)) * 2;  // 110592
    cudaFuncSetAttribute(gemm_h<0>, cudaFuncAttributeMaxDynamicSharedMemorySize, smemN);
    cudaFuncSetAttribute(gemm_h<1>, cudaFuncAttributeMaxDynamicSharedMemorySize, smemT);

    dim3 blk(256);
    const long sQKV_b = (long)SEQ * HEADS * HDIM;   // 4194304
    const long sSc_b  = (long)HEADS * SEQ * SEQ;    // 33554432
    const long sSc_h  = (long)SEQ * SEQ;            // 1048576

    // launches 1-5 (ncu skips these; #6 is the first big GEMM)
    rot_table_kernel<<<64, 256>>>();
    f2h_kernel<<<8192, 256>>>(x,  xh);
    f2h_kernel<<<8192, 256>>>(wq, wqh);
    f2h_kernel<<<8192, 256>>>(wk, wkh);
    f2h_kernel<<<8192, 256>>>(wv, wvh);

    // Q projection (launch #6 — profiled)
    gemm_h<0><<<dim3(32, 32, 1), blk, smemN>>>(xh, wqh, fb, 4096, 4096, 4096,
                                               0, 0, 0, 0, 0, 0, 1, DMODEL / BK);
    bias_rot_h_kernel<<<2048, 256>>>(fb, wq_b, qh);

    gemm_h<0><<<dim3(32, 32, 1), blk, smemN>>>(xh, wkh, fb, 4096, 4096, 4096,
                                               0, 0, 0, 0, 0, 0, 1, DMODEL / BK);
    bias_rot_h_kernel<<<2048, 256>>>(fb, wk_b, kh);

    gemm_h<0><<<dim3(32, 32, 1), blk, smemN>>>(xh, wvh, fb, 4096, 4096, 4096,
                                               0, 0, 0, 0, 0, 0, 1, DMODEL / BK);
    bias_f2h_kernel<<<16384, 256>>>(fb, wv_b, vh);

    f2h_kernel<<<8192, 256>>>(wo, woh);

    // scores[b,h,q,k] = Q . K^T
    gemm_h<1><<<dim3(8, 8, 128), blk, smemT>>>(qh, kh, sc, 4096, 4096, 1024,
                                               sQKV_b, 128, sQKV_b, 128, sSc_b, sSc_h,
                                               HEADS, HDIM / BK);

    softmax_kernel<<<16384, 256>>>(sc, attn_bias, ph, 0.08838834764831845f);

    // O[b,s,h,d] = P . V
    gemm_h<0><<<dim3(1, 8, 128), blk, smemN>>>(ph, vh, fb, 1024, 4096, 4096,
                                               sSc_b, sSc_h, sQKV_b, 128, sQKV_b, 128,
                                               HEADS, SEQ / BK);
    f2h_kernel<<<8192, 256>>>(fb, oh);

    // out = O . wo + wo_bias
    gemm_h<0><<<dim3(32, 32, 1), blk, smemN>>>(oh, woh, out, 4096, 4096, 4096,
                                               0, 0, 0, 0, 0, 0, 1, DMODEL / BK);
    bias_add_kernel<<<16384, 256>>>(out, wo_b);
}

// round 7
// speedup vs baseline: 5.6639x; 1.0120x over previous
#include <cuda_runtime.h>
#include <cuda_fp16.h>
#include <mma.h>
#include <cstdint>

using namespace nvcuda;

// Problem constants
#define BATCH 4
#define SEQ   1024
#define DMODEL 4096
#define HEADS 32
#define HDIM  128
#define ROTARY 32
#define MAXPOS 10000

// GEMM tiling (fp16 operands, fp32 accum)
#define BM 128
#define BN 128
#define BK 64
#define PADH 8      // 8 halfs = 16B pad
#define ST 3        // pipeline stages
#define EXP_SHIFT 8.0f

// Scratch (device globals; no allocation allowed)
__device__ __half g_xh [(long)DMODEL*DMODEL];           // fp16 x
__device__ __half g_wqh[(long)DMODEL*DMODEL];           // fp16 weights
__device__ __half g_wkh[(long)DMODEL*DMODEL];
__device__ __half g_wvh[(long)DMODEL*DMODEL];
__device__ __half g_woh[(long)DMODEL*DMODEL];
__device__ float  g_f  [(long)BATCH*SEQ*HEADS*HDIM];    // fp32 GEMM out scratch
__device__ __half g_qh [(long)BATCH*SEQ*HEADS*HDIM];    // fp16 q (post bias+rotary)
__device__ __half g_kh [(long)BATCH*SEQ*HEADS*HDIM];
__device__ __half g_vh [(long)BATCH*SEQ*HEADS*HDIM];
__device__ __half g_oh [(long)BATCH*SEQ*HEADS*HDIM];
__device__ __half g_ph [(long)BATCH*HEADS*SEQ*SEQ];     // fp16 unnormalized probs 256MB
__device__ float  g_rsum[(long)BATCH*HEADS*SEQ];        // row sums
__device__ float2 g_rot[SEQ*16];

// ---------------------------------------------------------------------------
// helpers
// ---------------------------------------------------------------------------
__device__ __forceinline__ void cp16(uint32_t saddr, const void* gptr) {
    asm volatile("cp.async.cg.shared.global [%0], [%1], 16;\n" :: "r"(saddr), "l"(gptr));
}
__device__ __forceinline__ void cp_commit() { asm volatile("cp.async.commit_group;\n"); }
__device__ __forceinline__ void cp_wait1()  { asm volatile("cp.async.wait_group 1;\n"); }

// ---------------------------------------------------------------------------
// fp16 GEMM, fp32 accumulate: C[M,N] = A[M,K] * B[K,N]
//   TRANSB: logical B[k,n] = Bp[n*ldb + k]  (col-major fragments)
//   EPI 0: plain fp32 store to Cf
//   EPI 2: QK epilogue: p = exp(acc*scale + attn_bias - 8), fp16 store to Ch
//   EPI 3: PV epilogue: o = acc / rsum[row], fp16 store to Ch
//   3-stage cp.async pipeline, BK=64, 2 CTAs/SM.
// ---------------------------------------------------------------------------
template<int TRANSB, int EPI>
__global__ __launch_bounds__(256, 2) void gemm_h(
    const __half* __restrict__ Ab, const __half* __restrict__ Bb,
    float* __restrict__ Cf, __half* __restrict__ Ch,
    const float* __restrict__ ebias, const float* __restrict__ rsum, float scale,
    int lda, int ldb, int ldc,
    long sAb, long sAh, long sBb, long sBh, long sCb, long sCh,
    int Hb, int KT)
{
    constexpr int ASZ = BM * (BK + PADH);                               // 9216 halfs
    constexpr int BSZ = TRANSB ? BN * (BK + PADH) : BK * (BN + PADH);   // 9216 / 8704
    extern __shared__ __half smh[];
    __half* As = smh;              // [ST][ASZ]
    __half* Bs = smh + ST * ASZ;   // [ST][BSZ]

    int z = blockIdx.z;
    int bb = z / Hb, hh = z % Hb;
    const __half* A = Ab + bb * sAb + hh * sAh;
    const __half* B = Bb + bb * sBb + hh * sBh;

    int rowBase = blockIdx.y * BM;
    int colBase = blockIdx.x * BN;

    int tid = threadIdx.x;
    int wid = tid >> 5;
    int warpRow = (wid & 3) * 32;   // 4 warps along M
    int warpCol = (wid >> 2) * 64;  // 2 warps along N

    // loader indices
    int lr = tid >> 3;           // 0..31
    int lc = (tid & 7) * 8;      // 0,8,..,56 (halfs)
    int br = tid >> 4;           // 0..15
    int bc = (tid & 15) * 8;     // 0..120 (halfs)

    uint32_t sA = (uint32_t)__cvta_generic_to_shared(As);
    uint32_t sB = (uint32_t)__cvta_generic_to_shared(Bs);

    wmma::fragment<wmma::accumulator, 16, 16, 16, float> c[2][4];
#pragma unroll
    for (int i = 0; i < 2; i++)
#pragma unroll
        for (int j = 0; j < 4; j++) wmma::fill_fragment(c[i][j], 0.0f);

    auto loadStage = [&](int kt, int buf) {
        uint32_t a0 = sA + (uint32_t)(buf * ASZ) * 2u;
#pragma unroll
        for (int p = 0; p < 4; p++) {
            int r = lr + p * 32;
            cp16(a0 + (uint32_t)(r * (BK + PADH) + lc) * 2u,
                 &A[(long)(rowBase + r) * lda + kt + lc]);
        }
        uint32_t b0 = sB + (uint32_t)(buf * BSZ) * 2u;
        if (TRANSB) {
#pragma unroll
            for (int p = 0; p < 4; p++) {
                int n = lr + p * 32;
                cp16(b0 + (uint32_t)(n * (BK + PADH) + lc) * 2u,
                     &B[(long)(colBase + n) * ldb + kt + lc]);
            }
        } else {
#pragma unroll
            for (int p = 0; p < 4; p++) {
                int r = br + p * 16;
                cp16(b0 + (uint32_t)(r * (BN + PADH) + bc) * 2u,
                     &B[(long)(kt + r) * ldb + colBase + bc]);
            }
        }
    };

    // prologue: stages 0 and 1
    loadStage(0, 0); cp_commit();
    if (1 < KT) loadStage(BK, 1);
    cp_commit();

    for (int it = 0; it < KT; it++) {
        int s = it % ST;
        cp_wait1();                // stage `it` resident
        __syncthreads();
        int nxt = it + 2;
        if (nxt < KT) loadStage(nxt * BK, nxt % ST);
        cp_commit();               // keep group accounting aligned

        const __half* Ap = As + s * ASZ;
        const __half* Bp = Bs + s * BSZ;

#pragma unroll
        for (int kk = 0; kk < BK; kk += 16) {
            wmma::fragment<wmma::matrix_a, 16, 16, 16, __half, wmma::row_major> a0, a1;
            wmma::load_matrix_sync(a0, Ap + warpRow * (BK + PADH) + kk, BK + PADH);
            wmma::load_matrix_sync(a1, Ap + (warpRow + 16) * (BK + PADH) + kk, BK + PADH);
#pragma unroll
            for (int j = 0; j < 4; j++) {
                if constexpr (TRANSB) {
                    wmma::fragment<wmma::matrix_b, 16, 16, 16, __half, wmma::col_major> bf;
                    wmma::load_matrix_sync(bf, Bp + (warpCol + 16 * j) * (BK + PADH) + kk, BK + PADH);
                    wmma::mma_sync(c[0][j], a0, bf, c[0][j]);
                    wmma::mma_sync(c[1][j], a1, bf, c[1][j]);
                } else {
                    wmma::fragment<wmma::matrix_b, 16, 16, 16, __half, wmma::row_major> bf;
                    wmma::load_matrix_sync(bf, Bp + kk * (BN + PADH) + warpCol + 16 * j, BN + PADH);
                    wmma::mma_sync(c[0][j], a0, bf, c[0][j]);
                    wmma::mma_sync(c[1][j], a1, bf, c[1][j]);
                }
            }
        }
    }

    if constexpr (EPI == 0) {
        float* C = Cf + bb * sCb + hh * sCh;
#pragma unroll
        for (int i = 0; i < 2; i++)
#pragma unroll
            for (int j = 0; j < 4; j++)
                wmma::store_matrix_sync(
                    C + (long)(rowBase + warpRow + 16 * i) * ldc + colBase + warpCol + 16 * j,
                    c[i][j], ldc, wmma::mem_row_major);
    } else {
        // stage the 128x128 fp32 tile through smem (pipeline buffers are free now)
        __syncthreads();
        float* Ss = (float*)smh;            // [128][132]
#pragma unroll
        for (int i = 0; i < 2; i++)
#pragma unroll
            for (int j = 0; j < 4; j++)
                wmma::store_matrix_sync(
                    Ss + (warpRow + 16 * i) * 132 + warpCol + 16 * j,
                    c[i][j], 132, wmma::mem_row_major);
        __syncthreads();

        __half* Cp = Ch + bb * sCb + hh * sCh;
        if constexpr (EPI == 2) {
            // p = exp(s*scale + bias - EXP_SHIFT) -> fp16
            for (int e = tid * 4; e < BM * BN; e += 1024) {
                int r = e >> 7, cc = e & 127;
                float4 s4 = *(float4*)&Ss[r * 132 + cc];
                float4 b4 = *(const float4*)&ebias[(long)(rowBase + r) * SEQ + colBase + cc];
                float p0 = __expf(fmaf(s4.x, scale, b4.x) - EXP_SHIFT);
                float p1 = __expf(fmaf(s4.y, scale, b4.y) - EXP_SHIFT);
                float p2 = __expf(fmaf(s4.z, scale, b4.z) - EXP_SHIFT);
                float p3 = __expf(fmaf(s4.w, scale, b4.w) - EXP_SHIFT);
                __half2 h0 = __floats2half2_rn(p0, p1);
                __half2 h1 = __floats2half2_rn(p2, p3);
                uint2 o; o.x = *(uint32_t*)&h0; o.y = *(uint32_t*)&h1;
                *(uint2*)&Cp[(long)(rowBase + r) * ldc + colBase + cc] = o;
            }
        } else {  // EPI == 3: divide by row sum, fp16 store
            const float* rs = rsum + (long)z * SEQ;
            for (int e = tid * 4; e < BM * BN; e += 1024) {
                int r = e >> 7, cc = e & 127;
                float4 s4 = *(float4*)&Ss[r * 132 + cc];
                float inv = 1.0f / rs[rowBase + r];
                __half2 h0 = __floats2half2_rn(s4.x * inv, s4.y * inv);
                __half2 h1 = __floats2half2_rn(s4.z * inv, s4.w * inv);
                uint2 o; o.x = *(uint32_t*)&h0; o.y = *(uint32_t*)&h1;
                *(uint2*)&Cp[(long)(rowBase + r) * ldc + colBase + cc] = o;
            }
        }
    }
}

// ---------------------------------------------------------------------------
// row sums of fp16 P~: one warp per row of 1024
// ---------------------------------------------------------------------------
__global__ void rowsum_kernel(const __half* __restrict__ p, float* __restrict__ rs)
{
    long row = (long)blockIdx.x * 8 + (threadIdx.x >> 5);
    int lane = threadIdx.x & 31;
    const __half* pr = p + row * SEQ;
    float s = 0.0f;
#pragma unroll
    for (int i = 0; i < 4; i++) {
        uint4 u = *(const uint4*)&pr[lane * 8 + i * 256];
        __half2* hh = (__half2*)&u;
#pragma unroll
        for (int k = 0; k < 4; k++) {
            float2 f = __half22float2(hh[k]);
            s += f.x + f.y;
        }
    }
#pragma unroll
    for (int o = 16; o; o >>= 1) s += __shfl_xor_sync(0xffffffffu, s, o);
    if (lane == 0) rs[row] = s;
}

// ---------------------------------------------------------------------------
// f32 -> f16 convert (RN), 8 elems/thread
// ---------------------------------------------------------------------------
__global__ void f2h_kernel(const float* __restrict__ in, __half* __restrict__ out)
{
    long i = ((long)blockIdx.x * blockDim.x + threadIdx.x) * 8;
    float4 a = *(const float4*)&in[i];
    float4 b = *(const float4*)&in[i + 4];
    __half2 h0 = __floats2half2_rn(a.x, a.y);
    __half2 h1 = __floats2half2_rn(a.z, a.w);
    __half2 h2 = __floats2half2_rn(b.x, b.y);
    __half2 h3 = __floats2half2_rn(b.z, b.w);
    uint4 o;
    o.x = *(uint32_t*)&h0; o.y = *(uint32_t*)&h1;
    o.z = *(uint32_t*)&h2; o.w = *(uint32_t*)&h3;
    *(uint4*)&out[i] = o;
}

// bias add (fp32) then f16 convert, N = 4096 (for V)
__global__ void bias_f2h_kernel(const float* __restrict__ in,
                                const float* __restrict__ bias,
                                __half* __restrict__ out)
{
    long i = ((long)blockIdx.x * blockDim.x + threadIdx.x) * 4;
    int n = (int)(i & 4095);
    float4 v = *(const float4*)&in[i];
    float4 b = *(const float4*)&bias[n];
    __half2 h0 = __floats2half2_rn(v.x + b.x, v.y + b.y);
    __half2 h1 = __floats2half2_rn(v.z + b.z, v.w + b.w);
    uint2 o; o.x = *(uint32_t*)&h0; o.y = *(uint32_t*)&h1;
    *(uint2*)&out[i] = o;
}

// plain bias add fp32 (final output), N = 4096
__global__ void bias_add_kernel(float* __restrict__ C, const float* __restrict__ bias)
{
    long i = ((long)blockIdx.x * blockDim.x + threadIdx.x) * 4;
    int n = (int)(i & 4095);
    float4 v = *(float4*)&C[i];
    float4 b = *(const float4*)&bias[n];
    v.x += b.x; v.y += b.y; v.z += b.z; v.w += b.w;
    *(float4*)&C[i] = v;
}

// ---------------------------------------------------------------------------
// rotary table (double precision, matches numpy float64)
// ---------------------------------------------------------------------------
__global__ void rot_table_kernel()
{
    int idx = blockIdx.x * blockDim.x + threadIdx.x;
    if (idx >= SEQ * 16) return;
    int s = idx >> 4, i = idx & 15;
    const double log1e4_over16 = 0.57564627324851145;  // ln(10000)/16
    double ang = (double)(MAXPOS - SEQ + s) * exp(-(double)i * log1e4_over16);
    double sn, cs;
    sincos(ang, &sn, &cs);
    g_rot[idx] = make_float2((float)cs, (float)sn);
}

// fused bias + partial rotary + f16 convert for Q/K (fp32 in, f16 out)
__global__ void bias_rot_h_kernel(const float* __restrict__ t,
                                  const float* __restrict__ bias,
                                  __half* __restrict__ out)
{
    int idx = blockIdx.x * blockDim.x + threadIdx.x;   // B*S*H*4
    int quarter = idx & 3;
    int row = idx >> 2;                                // (b*S+s)*H + h
    int h = row & (HEADS - 1);
    int s = (row >> 5) & (SEQ - 1);
    const float* ptr = t + (long)row * HDIM + quarter * 32;
    const float* brow = bias + h * HDIM + quarter * 32;
    __half* optr = out + (long)row * HDIM + quarter * 32;

    float x[32];
#pragma unroll
    for (int j = 0; j < 8; j++) {
        float4 v = *(const float4*)&ptr[j * 4];
        float4 b = *(const float4*)&brow[j * 4];
        x[j*4+0] = v.x + b.x; x[j*4+1] = v.y + b.y;
        x[j*4+2] = v.z + b.z; x[j*4+3] = v.w + b.w;
    }

    if (quarter == 0) {
        float y[32];
#pragma unroll
        for (int i = 0; i < 16; i++) {
            float2 cs = g_rot[s * 16 + i];
            float a = x[i], b = x[16 + i];
            y[2*i]   = (float)((double)a * (double)cs.x - (double)b * (double)cs.y);
            y[2*i+1] = (float)((double)a * (double)cs.y + (double)b * (double)cs.x);
        }
#pragma unroll
        for (int i = 0; i < 16; i++) {
            __half2 hh = __floats2half2_rn(y[2*i], y[2*i+1]);
            *(uint32_t*)&optr[2*i] = *(uint32_t*)&hh;
        }
    } else {
#pragma unroll
        for (int i = 0; i < 16; i++) {
            __half2 hh = __floats2half2_rn(x[2*i], x[2*i+1]);
            *(uint32_t*)&optr[2*i] = *(uint32_t*)&hh;
        }
    }
}

// ---------------------------------------------------------------------------
extern "C" void kernel_launch(void* const* d_in, const int* in_sizes, int n_in,
                              void* d_out, int out_size)
{
    const float* x         = (const float*)d_in[0];
    const float* attn_bias = (const float*)d_in[1];
    const float* wq        = (const float*)d_in[2];
    const float* wq_b      = (const float*)d_in[3];
    const float* wk        = (const float*)d_in[4];
    const float* wk_b      = (const float*)d_in[5];
    const float* wv        = (const float*)d_in[6];
    const float* wv_b      = (const float*)d_in[7];
    const float* wo        = (const float*)d_in[8];
    const float* wo_b      = (const float*)d_in[9];
    float* out = (float*)d_out;

    __half *xh, *wqh, *wkh, *wvh, *woh, *qh, *kh, *vh, *oh, *ph;
    float *fb, *rsum;
    cudaGetSymbolAddress((void**)&xh,  g_xh);
    cudaGetSymbolAddress((void**)&wqh, g_wqh);
    cudaGetSymbolAddress((void**)&wkh, g_wkh);
    cudaGetSymbolAddress((void**)&wvh, g_wvh);
    cudaGetSymbolAddress((void**)&woh, g_woh);
    cudaGetSymbolAddress((void**)&fb,  g_f);
    cudaGetSymbolAddress((void**)&qh,  g_qh);
    cudaGetSymbolAddress((void**)&kh,  g_kh);
    cudaGetSymbolAddress((void**)&vh,  g_vh);
    cudaGetSymbolAddress((void**)&oh,  g_oh);
    cudaGetSymbolAddress((void**)&ph,  g_ph);
    cudaGetSymbolAddress((void**)&rsum, g_rsum);

    // dynamic smem (bytes)
    const int smemN = (ST * BM * (BK + PADH) + ST * BK * (BN + PADH)) * 2;  // 107520
    const int smemT = (ST * BM * (BK + PADH) + ST * BN * (BK + PADH)) * 2;  // 110592
    cudaFuncSetAttribute(gemm_h<0,0>, cudaFuncAttributeMaxDynamicSharedMemorySize, smemN);
    cudaFuncSetAttribute(gemm_h<1,2>, cudaFuncAttributeMaxDynamicSharedMemorySize, smemT);
    cudaFuncSetAttribute(gemm_h<0,3>, cudaFuncAttributeMaxDynamicSharedMemorySize, smemN);

    dim3 blk(256);
    const long sQKV_b = (long)SEQ * HEADS * HDIM;   // 4194304
    const long sP_b   = (long)HEADS * SEQ * SEQ;    // 33554432
    const long sP_h   = (long)SEQ * SEQ;            // 1048576
    const float scale = 0.08838834764831845f;

    // launches 1-5 (ncu profiles #6 = Q projection GEMM)
    rot_table_kernel<<<64, 256>>>();
    f2h_kernel<<<8192, 256>>>(x,  xh);
    f2h_kernel<<<8192, 256>>>(wq, wqh);
    f2h_kernel<<<8192, 256>>>(wk, wkh);
    f2h_kernel<<<8192, 256>>>(wv, wvh);

    // Q projection (launch #6 — profiled)
    gemm_h<0,0><<<dim3(32, 32, 1), blk, smemN>>>(xh, wqh, fb, nullptr, nullptr, nullptr, 0.f,
                                                 4096, 4096, 4096, 0, 0, 0, 0, 0, 0, 1, DMODEL / BK);
    bias_rot_h_kernel<<<2048, 256>>>(fb, wq_b, qh);

    gemm_h<0,0><<<dim3(32, 32, 1), blk, smemN>>>(xh, wkh, fb, nullptr, nullptr, nullptr, 0.f,
                                                 4096, 4096, 4096, 0, 0, 0, 0, 0, 0, 1, DMODEL / BK);
    bias_rot_h_kernel<<<2048, 256>>>(fb, wk_b, kh);

    gemm_h<0,0><<<dim3(32, 32, 1), blk, smemN>>>(xh, wvh, fb, nullptr, nullptr, nullptr, 0.f,
                                                 4096, 4096, 4096, 0, 0, 0, 0, 0, 0, 1, DMODEL / BK);
    bias_f2h_kernel<<<16384, 256>>>(fb, wv_b, vh);

    f2h_kernel<<<8192, 256>>>(wo, woh);

    // P~[b,h,q,k] = exp(scale * Q.K^T + bias - 8) directly in epilogue (fp16)
    gemm_h<1,2><<<dim3(8, 8, 128), blk, smemT>>>(qh, kh, nullptr, ph, attn_bias, nullptr, scale,
                                                 4096, 4096, 1024,
                                                 sQKV_b, 128, sQKV_b, 128, sP_b, sP_h,
                                                 HEADS, HDIM / BK);

    rowsum_kernel<<<16384, 256>>>(ph, rsum);

    // O[b,s,h,d] = (P~ . V) / rsum  -> fp16 directly
    gemm_h<0,3><<<dim3(1, 8, 128), blk, smemN>>>(ph, vh, nullptr, oh, nullptr, rsum, 0.f,
                                                 1024, 4096, 4096,
                                                 sP_b, sP_h, sQKV_b, 128, sQKV_b, 128,
                                                 HEADS, SEQ / BK);

    // out = O . wo + wo_bias
    gemm_h<0,0><<<dim3(32, 32, 1), blk, smemN>>>(oh, woh, out, nullptr, nullptr, nullptr, 0.f,
                                                 4096, 4096, 4096, 0, 0, 0, 0, 0, 0, 1, DMODEL / BK);
    bias_add_kernel<<<16384, 256>>>(out, wo_b);
}

// round 9
// speedup vs baseline: 6.4057x; 1.1310x over previous
#include <cuda_runtime.h>
#include <cuda_fp16.h>
#include <mma.h>
#include <cstdint>

using namespace nvcuda;

// Problem constants
#define BATCH 4
#define SEQ   1024
#define DMODEL 4096
#define HEADS 32
#define HDIM  128
#define ROTARY 32
#define MAXPOS 10000
#define NQKV  12288                       // 3*DMODEL
#define QKVN  ((long)BATCH*SEQ*HEADS*HDIM)

// GEMM tiling (fp16 operands, fp32 accum)
#define BM 128
#define BN 128
#define BK 64
#define PADH 8      // 8 halfs = 16B pad
#define ST 3        // pipeline stages
#define EXP_SHIFT 8.0f

// Scratch (device globals; no allocation allowed)
__device__ __half g_xh   [(long)DMODEL*DMODEL];          // fp16 x
__device__ __half g_wqkvh[(long)DMODEL*NQKV];            // fp16 [Wq|Wk|Wv], [4096][12288]
__device__ __half g_woh  [(long)DMODEL*DMODEL];          // fp16 wo
__device__ __half g_qkvh [3*QKVN];                       // fp16 q,k,v [B,S,H,HD] each
__device__ __half g_oh   [QKVN];                         // fp16 attention output
__device__ __half g_ph   [(long)BATCH*HEADS*SEQ*SEQ];    // fp16 unnormalized probs 256MB
__device__ float  g_rsum [(long)BATCH*HEADS*SEQ];        // row sums (atomic)
__device__ float  g_bqkv [NQKV];                         // concat biases
__device__ float2 g_rot  [SEQ*16];                       // rotary cos/sin

// ---------------------------------------------------------------------------
// helpers
// ---------------------------------------------------------------------------
__device__ __forceinline__ void cp16(uint32_t saddr, const void* gptr) {
    asm volatile("cp.async.cg.shared.global [%0], [%1], 16;\n" :: "r"(saddr), "l"(gptr));
}
__device__ __forceinline__ void cp_commit() { asm volatile("cp.async.commit_group;\n"); }
__device__ __forceinline__ void cp_wait1()  { asm volatile("cp.async.wait_group 1;\n"); }

// ---------------------------------------------------------------------------
// fp16 GEMM, fp32 accumulate: C[M,N] = A[M,K] * B[K,N]
//   TRANSB: logical B[k,n] = Bp[n*ldb + k]
//   EPI 1: fused QKV epilogue: +bias, partial rotary (q/k), f16 -> g_qkvh
//   EPI 2: QK epilogue: p=exp(acc*scale+attn_bias-8) -> fp16 Ch, + atomic rowsum
//   EPI 3: PV epilogue: o = acc / rsum[row] -> fp16 Ch
//   EPI 5: final epilogue: acc + ebias[n] -> fp32 Cf
// ---------------------------------------------------------------------------
template<int TRANSB, int EPI>
__global__ __launch_bounds__(256, 2) void gemm_h(
    const __half* __restrict__ Ab, const __half* __restrict__ Bb,
    float* __restrict__ Cf, __half* __restrict__ Ch,
    const float* __restrict__ ebias, float scale,
    int lda, int ldb, int ldc,
    long sAb, long sAh, long sBb, long sBh, long sCb, long sCh,
    int Hb, int KT)
{
    constexpr int ASZ = BM * (BK + PADH);                               // 9216 halfs
    constexpr int BSZ = TRANSB ? BN * (BK + PADH) : BK * (BN + PADH);   // 9216 / 8704
    extern __shared__ __half smh[];
    __half* As = smh;              // [ST][ASZ]
    __half* Bs = smh + ST * ASZ;   // [ST][BSZ]

    int z = blockIdx.z;
    int bb = z / Hb, hh = z % Hb;
    const __half* A = Ab + bb * sAb + hh * sAh;
    const __half* B = Bb + bb * sBb + hh * sBh;

    int rowBase = blockIdx.y * BM;
    int colBase = blockIdx.x * BN;

    int tid = threadIdx.x;
    int wid = tid >> 5;
    int lane = tid & 31;
    int warpRow = (wid & 3) * 32;   // 4 warps along M
    int warpCol = (wid >> 2) * 64;  // 2 warps along N

    // loader indices
    int lr = tid >> 3;           // 0..31
    int lc = (tid & 7) * 8;      // halfs
    int br = tid >> 4;           // 0..15
    int bc = (tid & 15) * 8;     // halfs

    uint32_t sA = (uint32_t)__cvta_generic_to_shared(As);
    uint32_t sB = (uint32_t)__cvta_generic_to_shared(Bs);

    wmma::fragment<wmma::accumulator, 16, 16, 16, float> c[2][4];
#pragma unroll
    for (int i = 0; i < 2; i++)
#pragma unroll
        for (int j = 0; j < 4; j++) wmma::fill_fragment(c[i][j], 0.0f);

    auto loadStage = [&](int kt, int buf) {
        uint32_t a0 = sA + (uint32_t)(buf * ASZ) * 2u;
#pragma unroll
        for (int p = 0; p < 4; p++) {
            int r = lr + p * 32;
            cp16(a0 + (uint32_t)(r * (BK + PADH) + lc) * 2u,
                 &A[(long)(rowBase + r) * lda + kt + lc]);
        }
        uint32_t b0 = sB + (uint32_t)(buf * BSZ) * 2u;
        if (TRANSB) {
#pragma unroll
            for (int p = 0; p < 4; p++) {
                int n = lr + p * 32;
                cp16(b0 + (uint32_t)(n * (BK + PADH) + lc) * 2u,
                     &B[(long)(colBase + n) * ldb + kt + lc]);
            }
        } else {
#pragma unroll
            for (int p = 0; p < 4; p++) {
                int r = br + p * 16;
                cp16(b0 + (uint32_t)(r * (BN + PADH) + bc) * 2u,
                     &B[(long)(kt + r) * ldb + colBase + bc]);
            }
        }
    };

    loadStage(0, 0); cp_commit();
    if (1 < KT) loadStage(BK, 1);
    cp_commit();

    for (int it = 0; it < KT; it++) {
        int s = it % ST;
        cp_wait1();
        __syncthreads();
        int nxt = it + 2;
        if (nxt < KT) loadStage(nxt * BK, nxt % ST);
        cp_commit();

        const __half* Ap = As + s * ASZ;
        const __half* Bp = Bs + s * BSZ;

#pragma unroll
        for (int kk = 0; kk < BK; kk += 16) {
            wmma::fragment<wmma::matrix_a, 16, 16, 16, __half, wmma::row_major> a0, a1;
            wmma::load_matrix_sync(a0, Ap + warpRow * (BK + PADH) + kk, BK + PADH);
            wmma::load_matrix_sync(a1, Ap + (warpRow + 16) * (BK + PADH) + kk, BK + PADH);
#pragma unroll
            for (int j = 0; j < 4; j++) {
                if constexpr (TRANSB) {
                    wmma::fragment<wmma::matrix_b, 16, 16, 16, __half, wmma::col_major> bf;
                    wmma::load_matrix_sync(bf, Bp + (warpCol + 16 * j) * (BK + PADH) + kk, BK + PADH);
                    wmma::mma_sync(c[0][j], a0, bf, c[0][j]);
                    wmma::mma_sync(c[1][j], a1, bf, c[1][j]);
                } else {
                    wmma::fragment<wmma::matrix_b, 16, 16, 16, __half, wmma::row_major> bf;
                    wmma::load_matrix_sync(bf, Bp + kk * (BN + PADH) + warpCol + 16 * j, BN + PADH);
                    wmma::mma_sync(c[0][j], a0, bf, c[0][j]);
                    wmma::mma_sync(c[1][j], a1, bf, c[1][j]);
                }
            }
        }
    }

    // ---- epilogue: stage fp32 tile through smem ----
    __syncthreads();
    float* Ss = (float*)smh;            // [128][132]
#pragma unroll
    for (int i = 0; i < 2; i++)
#pragma unroll
        for (int j = 0; j < 4; j++)
            wmma::store_matrix_sync(
                Ss + (warpRow + 16 * i) * 132 + warpCol + 16 * j,
                c[i][j], 132, wmma::mem_row_major);
    __syncthreads();

    if constexpr (EPI == 1) {
        // fused QKV: bias + (partial rotary for q/k) + f16 -> g_qkvh[proj]
        int proj = colBase >> 12;            // 0=q, 1=k, 2=v
        int h = (colBase >> 7) & 31;
        __half* outBase = g_qkvh + (long)proj * QKVN;
        for (int u = tid; u < 512; u += 256) {
            int r = u >> 2, quarter = u & 3;
            int m = rowBase + r;
            int s = m & (SEQ - 1);
            const float* srow = Ss + r * 132 + quarter * 32;
            const float* brow = g_bqkv + proj * DMODEL + h * HDIM + quarter * 32;
            __half* optr = outBase + ((long)m * HEADS + h) * HDIM + quarter * 32;
            float xv[32];
#pragma unroll
            for (int j = 0; j < 8; j++) {
                float4 v = *(const float4*)&srow[j * 4];
                float4 b = *(const float4*)&brow[j * 4];
                xv[j*4+0] = v.x + b.x; xv[j*4+1] = v.y + b.y;
                xv[j*4+2] = v.z + b.z; xv[j*4+3] = v.w + b.w;
            }
            if (proj < 2 && quarter == 0) {
                float y[32];
#pragma unroll
                for (int i = 0; i < 16; i++) {
                    float2 cs = g_rot[s * 16 + i];
                    float a = xv[i], b = xv[16 + i];
                    y[2*i]   = (float)((double)a * (double)cs.x - (double)b * (double)cs.y);
                    y[2*i+1] = (float)((double)a * (double)cs.y + (double)b * (double)cs.x);
                }
#pragma unroll
                for (int i = 0; i < 16; i++) {
                    __half2 hh2 = __floats2half2_rn(y[2*i], y[2*i+1]);
                    *(uint32_t*)&optr[2*i] = *(uint32_t*)&hh2;
                }
            } else {
#pragma unroll
                for (int i = 0; i < 16; i++) {
                    __half2 hh2 = __floats2half2_rn(xv[2*i], xv[2*i+1]);
                    *(uint32_t*)&optr[2*i] = *(uint32_t*)&hh2;
                }
            }
        }
    } else if constexpr (EPI == 2) {
        // p = exp(s*scale + bias - EXP_SHIFT) -> fp16; atomic row sums
        __half* Cp = Ch + bb * sCb + hh * sCh;
        float* rs = g_rsum + (long)z * SEQ + rowBase;
#pragma unroll
        for (int itn = 0; itn < 16; itn++) {
            int e = tid * 4 + itn * 1024;
            int r = e >> 7, cc = e & 127;        // whole warp shares r
            float4 s4 = *(float4*)&Ss[r * 132 + cc];
            float4 b4 = *(const float4*)&ebias[(long)(rowBase + r) * SEQ + colBase + cc];
            float p0 = __expf(fmaf(s4.x, scale, b4.x) - EXP_SHIFT);
            float p1 = __expf(fmaf(s4.y, scale, b4.y) - EXP_SHIFT);
            float p2 = __expf(fmaf(s4.z, scale, b4.z) - EXP_SHIFT);
            float p3 = __expf(fmaf(s4.w, scale, b4.w) - EXP_SHIFT);
            __half2 h0 = __floats2half2_rn(p0, p1);
            __half2 h1 = __floats2half2_rn(p2, p3);
            uint2 o; o.x = *(uint32_t*)&h0; o.y = *(uint32_t*)&h1;
            *(uint2*)&Cp[(long)(rowBase + r) * ldc + colBase + cc] = o;
            float psum = (p0 + p1) + (p2 + p3);
#pragma unroll
            for (int off = 16; off; off >>= 1)
                psum += __shfl_xor_sync(0xffffffffu, psum, off);
            if (lane == 0) atomicAdd(&rs[r], psum);
        }
    } else if constexpr (EPI == 3) {
        // o = acc / rsum[row] -> fp16
        __half* Cp = Ch + bb * sCb + hh * sCh;
        const float* rs = g_rsum + (long)z * SEQ;
#pragma unroll
        for (int itn = 0; itn < 16; itn++) {
            int e = tid * 4 + itn * 1024;
            int r = e >> 7, cc = e & 127;
            float4 s4 = *(float4*)&Ss[r * 132 + cc];
            float inv = 1.0f / rs[rowBase + r];
            __half2 h0 = __floats2half2_rn(s4.x * inv, s4.y * inv);
            __half2 h1 = __floats2half2_rn(s4.z * inv, s4.w * inv);
            uint2 o; o.x = *(uint32_t*)&h0; o.y = *(uint32_t*)&h1;
            *(uint2*)&Cp[(long)(rowBase + r) * ldc + colBase + cc] = o;
        }
    } else {
        // EPI == 5: acc + bias[n] -> fp32
#pragma unroll
        for (int itn = 0; itn < 16; itn++) {
            int e = tid * 4 + itn * 1024;
            int r = e >> 7, cc = e & 127;
            float4 s4 = *(float4*)&Ss[r * 132 + cc];
            float4 b4 = *(const float4*)&ebias[colBase + cc];
            s4.x += b4.x; s4.y += b4.y; s4.z += b4.z; s4.w += b4.w;
            *(float4*)&Cf[(long)(rowBase + r) * ldc + colBase + cc] = s4;
        }
    }
}

// ---------------------------------------------------------------------------
// rotary table (double precision) + concat QKV biases into g_bqkv
// ---------------------------------------------------------------------------
__global__ void rot_bias_kernel(const float* __restrict__ bq,
                                const float* __restrict__ bk,
                                const float* __restrict__ bv)
{
    int idx = blockIdx.x * blockDim.x + threadIdx.x;   // 16384 threads
    if (idx < SEQ * 16) {
        int s = idx >> 4, i = idx & 15;
        const double log1e4_over16 = 0.57564627324851145;  // ln(10000)/16
        double ang = (double)(MAXPOS - SEQ + s) * exp(-(double)i * log1e4_over16);
        double sn, cs;
        sincos(ang, &sn, &cs);
        g_rot[idx] = make_float2((float)cs, (float)sn);
    }
    if (idx < NQKV) {
        float v = (idx < 4096) ? bq[idx] : (idx < 8192) ? bk[idx - 4096] : bv[idx - 8192];
        g_bqkv[idx] = v;
    }
}

// ---------------------------------------------------------------------------
// f32 -> f16 convert (RN), 8 elems/thread (square [4096][4096] layout)
// ---------------------------------------------------------------------------
__global__ void f2h_kernel(const float* __restrict__ in, __half* __restrict__ out)
{
    long i = ((long)blockIdx.x * blockDim.x + threadIdx.x) * 8;
    float4 a = *(const float4*)&in[i];
    float4 b = *(const float4*)&in[i + 4];
    __half2 h0 = __floats2half2_rn(a.x, a.y);
    __half2 h1 = __floats2half2_rn(a.z, a.w);
    __half2 h2 = __floats2half2_rn(b.x, b.y);
    __half2 h3 = __floats2half2_rn(b.z, b.w);
    uint4 o;
    o.x = *(uint32_t*)&h0; o.y = *(uint32_t*)&h1;
    o.z = *(uint32_t*)&h2; o.w = *(uint32_t*)&h3;
    *(uint4*)&out[i] = o;
}

// f32 [4096][4096] -> f16 column slice of g_wqkvh [4096][12288]
__global__ void f2h_col_kernel(const float* __restrict__ in, int colOff)
{
    long i = ((long)blockIdx.x * blockDim.x + threadIdx.x) * 8;
    int row = (int)(i >> 12), col = (int)(i & 4095);
    float4 a = *(const float4*)&in[i];
    float4 b = *(const float4*)&in[i + 4];
    __half2 h0 = __floats2half2_rn(a.x, a.y);
    __half2 h1 = __floats2half2_rn(a.z, a.w);
    __half2 h2 = __floats2half2_rn(b.x, b.y);
    __half2 h3 = __floats2half2_rn(b.z, b.w);
    uint4 o;
    o.x = *(uint32_t*)&h0; o.y = *(uint32_t*)&h1;
    o.z = *(uint32_t*)&h2; o.w = *(uint32_t*)&h3;
    *(uint4*)&g_wqkvh[(long)row * NQKV + colOff + col] = o;
}

// zero g_rsum (131072 floats)
__global__ void zero_rsum_kernel()
{
    int i = (blockIdx.x * blockDim.x + threadIdx.x) * 4;
    *(float4*)&g_rsum[i] = make_float4(0.f, 0.f, 0.f, 0.f);
}

// ---------------------------------------------------------------------------
extern "C" void kernel_launch(void* const* d_in, const int* in_sizes, int n_in,
                              void* d_out, int out_size)
{
    const float* x         = (const float*)d_in[0];
    const float* attn_bias = (const float*)d_in[1];
    const float* wq        = (const float*)d_in[2];
    const float* wq_b      = (const float*)d_in[3];
    const float* wk        = (const float*)d_in[4];
    const float* wk_b      = (const float*)d_in[5];
    const float* wv        = (const float*)d_in[6];
    const float* wv_b      = (const float*)d_in[7];
    const float* wo        = (const float*)d_in[8];
    const float* wo_b      = (const float*)d_in[9];
    float* out = (float*)d_out;

    __half *xh, *woh, *qkvh, *oh, *ph;
    cudaGetSymbolAddress((void**)&xh,   g_xh);
    cudaGetSymbolAddress((void**)&woh,  g_woh);
    cudaGetSymbolAddress((void**)&qkvh, g_qkvh);
    cudaGetSymbolAddress((void**)&oh,   g_oh);
    cudaGetSymbolAddress((void**)&ph,   g_ph);
    __half* wqkvh;
    cudaGetSymbolAddress((void**)&wqkvh, g_wqkvh);
    __half* qh = qkvh;
    __half* kh = qkvh + QKVN;
    __half* vh = qkvh + 2 * QKVN;

    // dynamic smem (bytes)
    const int smemN = (ST * BM * (BK + PADH) + ST * BK * (BN + PADH)) * 2;  // 107520
    const int smemT = (ST * BM * (BK + PADH) + ST * BN * (BK + PADH)) * 2;  // 110592
    cudaFuncSetAttribute(gemm_h<0,1>, cudaFuncAttributeMaxDynamicSharedMemorySize, smemN);
    cudaFuncSetAttribute(gemm_h<1,2>, cudaFuncAttributeMaxDynamicSharedMemorySize, smemT);
    cudaFuncSetAttribute(gemm_h<0,3>, cudaFuncAttributeMaxDynamicSharedMemorySize, smemN);
    cudaFuncSetAttribute(gemm_h<0,5>, cudaFuncAttributeMaxDynamicSharedMemorySize, smemN);

    dim3 blk(256);
    const long sQKV_b = (long)SEQ * HEADS * HDIM;   // 4194304
    const long sP_b   = (long)HEADS * SEQ * SEQ;    // 33554432
    const long sP_h   = (long)SEQ * SEQ;            // 1048576
    const float scale = 0.08838834764831845f;

    // launches 1-5 (ncu profiles #6 = fused QKV GEMM)
    rot_bias_kernel<<<64, 256>>>(wq_b, wk_b, wv_b);
    f2h_kernel<<<8192, 256>>>(x, xh);
    f2h_col_kernel<<<8192, 256>>>(wq, 0);
    f2h_col_kernel<<<8192, 256>>>(wk, 4096);
    f2h_col_kernel<<<8192, 256>>>(wv, 8192);

    // fused QKV projection (launch #6 — profiled): C = X * [Wq|Wk|Wv],
    // epilogue does bias + partial rotary + f16 into g_qkvh
    gemm_h<0,1><<<dim3(96, 32, 1), blk, smemN>>>(xh, wqkvh, nullptr, nullptr, nullptr, 0.f,
                                                 4096, NQKV, 0, 0, 0, 0, 0, 0, 0, 1, DMODEL / BK);

    zero_rsum_kernel<<<128, 256>>>();
    f2h_kernel<<<8192, 256>>>(wo, woh);

    // P~ = exp(scale * Q.K^T + bias - 8) -> fp16, with atomic row sums
    gemm_h<1,2><<<dim3(8, 8, 128), blk, smemT>>>(qh, kh, nullptr, ph, attn_bias, scale,
                                                 4096, 4096, 1024,
                                                 sQKV_b, 128, sQKV_b, 128, sP_b, sP_h,
                                                 HEADS, HDIM / BK);

    // O = (P~ . V) / rsum -> fp16
    gemm_h<0,3><<<dim3(1, 8, 128), blk, smemN>>>(ph, vh, nullptr, oh, nullptr, 0.f,
                                                 1024, 4096, 4096,
                                                 sP_b, sP_h, sQKV_b, 128, sQKV_b, 128,
                                                 HEADS, SEQ / BK);

    // out = O . wo + wo_bias (fused in epilogue)
    gemm_h<0,5><<<dim3(32, 32, 1), blk, smemN>>>(oh, woh, out, nullptr, wo_b, 0.f,
                                                 4096, 4096, 4096, 0, 0, 0, 0, 0, 0, 1, DMODEL / BK);
}